// round 2
// baseline (speedup 1.0000x reference)
#include <cuda_runtime.h>

// Problem constants
#define N_VEC   32768      // B*H*W = 32*32*32
#define DIM     256        // e_dim (= C)
#define KC      1024       // n_e
#define HW      1024       // H*W
#define NB      32         // batch

// Tiling for argmin GEMM
#define TM      128
#define TN      64
#define NTHR    256

// Output layout (flattened reference tuple, float32)
#define ZQ_OFF    1
#define PERP_OFF  8388609
#define ENC_OFF   8388610
#define IDX_OFF   41943042ull

// Scratch (device globals -- no allocations allowed)
__device__ float g_cbT[DIM * KC];     // codebook transposed: [c][k]
__device__ float g_eNorm[KC];         // fp32(||e_k||^2), fp64-accumulated
__device__ int   g_idx[N_VEC];        // argmin indices
__device__ float g_lossSum;
__device__ int   g_counts[KC];

// ---------------------------------------------------------------------------
__global__ void initKernel() {
    int t = threadIdx.x;
    if (t < KC) g_counts[t] = 0;
    if (t == 0) g_lossSum = 0.0f;
}

// Transpose codebook [K][D] -> g_cbT [D][K] (coalesced both sides via smem)
__global__ void transposeCB(const float* __restrict__ cb) {
    __shared__ float tile[32][33];
    int k0 = blockIdx.x * 32;
    int c0 = blockIdx.y * 32;
    int x = threadIdx.x, y = threadIdx.y;   // block (32,8)
#pragma unroll
    for (int i = 0; i < 32; i += 8)
        tile[y + i][x] = cb[(k0 + y + i) * DIM + c0 + x];
    __syncthreads();
#pragma unroll
    for (int i = 0; i < 32; i += 8)
        g_cbT[(c0 + y + i) * KC + k0 + x] = tile[x][y + i];
}

// Per-code squared norms, fp64 accumulation -> fp32
__global__ void codeNorms(const float* __restrict__ cb) {
    int k = blockIdx.x;
    float v = cb[k * DIM + threadIdx.x];   // 256 threads
    double s = (double)v * (double)v;
#pragma unroll
    for (int o = 16; o > 0; o >>= 1) s += __shfl_down_sync(0xffffffffu, s, o);
    __shared__ double ws[8];
    int lane = threadIdx.x & 31, w = threadIdx.x >> 5;
    if (lane == 0) ws[w] = s;
    __syncthreads();
    if (threadIdx.x == 0) {
        double t = 0.0;
#pragma unroll
        for (int i = 0; i < 8; i++) t += ws[i];
        g_eNorm[k] = (float)t;
    }
}

// ---------------------------------------------------------------------------
// Argmin GEMM: per block, TM=128 vectors vs all 1024 codes (tiles of TN=64),
// depth D=256. smem: z tile [D][TM] (resident), code tile [D][TN] (streamed).
// Per-thread 8x4 register tile.
//
// Scoring EMULATES the reference's fp32 op sequence:
//   d = fl32( fl32(zn + en_k) - 2*dot_k )
// (zn = ||z||^2, en = ||e||^2; explicit __fadd_rn/__fsub_rn prevent FMA
// contraction). The rounding at magnitude ~256 collapses near-ties exactly
// like jnp does; ties are broken by LOWEST code index to match jnp.argmin.
// zn's low bits don't affect ordering (grid-aligned shift), so fp64->fp32
// zn is sufficient.
__global__ __launch_bounds__(NTHR) void argminKernel(const float* __restrict__ z) {
    extern __shared__ float smem[];
    float* zs   = smem;                        // DIM*TM = 32768 floats
    float* es   = smem + DIM * TM;             // DIM*TN = 16384 floats
    float* zn32 = smem + DIM * TM + DIM * TN;  // TM floats

    int n0 = blockIdx.x * TM;              // tile stays within one batch image
    const float* zbase = z + (size_t)(n0 / HW) * DIM * HW + (n0 % HW);
    int tid = threadIdx.x;

    // load z tile: z[b][c][hw0 + m], coalesced float4 over m
    for (int i = tid; i < DIM * TM / 4; i += NTHR) {
        int c = i >> 5, m4 = i & 31;
        *(float4*)(zs + c * TM + m4 * 4) =
            *(const float4*)(zbase + (size_t)c * HW + m4 * 4);
    }
    __syncthreads();

    // per-vector ||z||^2 in fp64 (two threads per vector), -> fp32
    {
        double* dp = (double*)es;   // 256 doubles, es free until kt loop
        int m = tid & (TM - 1), half = tid >> 7;
        double s = 0.0;
#pragma unroll 8
        for (int cc = 0; cc < DIM / 2; cc++) {
            float v = zs[(half * (DIM / 2) + cc) * TM + m];
            s += (double)v * (double)v;
        }
        dp[tid] = s;
        __syncthreads();
        if (tid < TM) zn32[tid] = (float)(dp[tid] + dp[tid + TM]);
        __syncthreads();
    }

    int tx = tid & 15;          // code dim (16 x 4 = 64)
    int ty = tid >> 4;          // vector dim (16 x 8 = 128)
    int m0 = ty * 8;

    float znr[8];
#pragma unroll
    for (int i = 0; i < 8; i++) znr[i] = zn32[m0 + i];

    float best[8];
    int   bidx[8];
#pragma unroll
    for (int i = 0; i < 8; i++) { best[i] = 3.4e38f; bidx[i] = 0; }

    for (int kt = 0; kt < KC / TN; kt++) {
        int k0 = kt * TN;
        __syncthreads();
        // load code tile from transposed codebook (coalesced over k)
        for (int i = tid; i < DIM * TN / 4; i += NTHR) {
            int c = i >> 4, k4 = i & 15;
            *(float4*)(es + c * TN + k4 * 4) =
                *(const float4*)(g_cbT + c * KC + k0 + k4 * 4);
        }
        __syncthreads();

        float acc[8][4];
#pragma unroll
        for (int i = 0; i < 8; i++)
#pragma unroll
            for (int j = 0; j < 4; j++) acc[i][j] = 0.0f;

#pragma unroll 4
        for (int c = 0; c < DIM; c++) {
            float4 za = *(const float4*)(zs + c * TM + m0);
            float4 zb = *(const float4*)(zs + c * TM + m0 + 4);
            float4 ev = *(const float4*)(es + c * TN + tx * 4);
            float zr[8] = {za.x, za.y, za.z, za.w, zb.x, zb.y, zb.z, zb.w};
            float er[4] = {ev.x, ev.y, ev.z, ev.w};
#pragma unroll
            for (int i = 0; i < 8; i++)
#pragma unroll
                for (int j = 0; j < 4; j++)
                    acc[i][j] = fmaf(zr[i], er[j], acc[i][j]);
        }

#pragma unroll
        for (int j = 0; j < 4; j++) {
            int k = k0 + tx * 4 + j;
            float en = g_eNorm[k];
#pragma unroll
            for (int i = 0; i < 8; i++) {
                // replicate ref: (zn + en) - 2*dot, two separate fp32 roundings
                float t1 = __fadd_rn(znr[i], en);
                float s  = __fsub_rn(t1, 2.0f * acc[i][j]);
                if (s < best[i]) { best[i] = s; bidx[i] = k; }
            }
        }
    }

    // cross-tx reduction (16 candidates per row), lowest-index tie-break
    __syncthreads();
    float* vred = es;                   // 128*16 floats
    int*   ired = (int*)(es + TM * 16); // 128*16 ints
#pragma unroll
    for (int i = 0; i < 8; i++) {
        vred[(m0 + i) * 16 + tx] = best[i];
        ired[(m0 + i) * 16 + tx] = bidx[i];
    }
    __syncthreads();
    if (tid < TM) {
        float bv = vred[tid * 16];
        int   bi = ired[tid * 16];
#pragma unroll
        for (int t = 1; t < 16; t++) {
            float v = vred[tid * 16 + t];
            int  ii = ired[tid * 16 + t];
            if (v < bv || (v == bv && ii < bi)) { bv = v; bi = ii; }
        }
        g_idx[n0 + tid] = bi;
    }
}

// ---------------------------------------------------------------------------
// z_q gather + straight-through + loss partial sums. 4 elems/thread.
__global__ void zqLossKernel(const float* __restrict__ z,
                             const float* __restrict__ cb,
                             float* __restrict__ out) {
    int i4 = blockIdx.x * blockDim.x + threadIdx.x;  // [0, 2097152)
    float4 zv = ((const float4*)z)[i4];
    int base = i4 << 2;
    int hw = base & (HW - 1);
    int c  = (base >> 10) & (DIM - 1);
    int b  = base >> 18;
    int n  = b * HW + hw;
    float zz[4] = {zv.x, zv.y, zv.z, zv.w};
    float ls = 0.0f;
#pragma unroll
    for (int j = 0; j < 4; j++) {
        int k = g_idx[n + j];
        float q = __ldg(cb + k * DIM + c);
        float d = q - zz[j];
        out[ZQ_OFF + base + j] = zz[j] + d;  // z + sg(z_q - z), ref rounding
        ls += d * d;
    }
#pragma unroll
    for (int o = 16; o > 0; o >>= 1) ls += __shfl_down_sync(0xffffffffu, ls, o);
    __shared__ float ws[8];
    int lane = threadIdx.x & 31, w = threadIdx.x >> 5;
    if (lane == 0) ws[w] = ls;
    __syncthreads();
    if (threadIdx.x == 0) {
        float t = 0.0f;
#pragma unroll
        for (int i = 0; i < 8; i++) t += ws[i];
        atomicAdd(&g_lossSum, t);
    }
}

// Zero the one-hot region (float2: ENC_OFF is 8B-aligned)
__global__ void zeroEnc(float* __restrict__ out) {
    size_t i = (size_t)blockIdx.x * blockDim.x + threadIdx.x;  // 16.7M
    float2* p = (float2*)(out + ENC_OFF);
    p[i] = make_float2(0.0f, 0.0f);
}

// Scatter one-hot ones, write indices (as float), histogram codes
__global__ void scatterKernel(float* __restrict__ out) {
    __shared__ int h[KC];
    int t = threadIdx.x;   // 1024
    h[t] = 0;
    __syncthreads();
    int n = blockIdx.x * 1024 + t;   // grid 32
    int k = g_idx[n];
    atomicAdd(&h[k], 1);
    out[ENC_OFF + (size_t)n * KC + k] = 1.0f;
    out[IDX_OFF + n] = (float)k;
    __syncthreads();
    if (h[t]) atomicAdd(&g_counts[t], h[t]);
}

__global__ void finalizeKernel(float* __restrict__ out) {
    int t = threadIdx.x;   // 1024
    float em = (float)g_counts[t] * (1.0f / (float)N_VEC);
    float v = em * logf(em + 1e-10f);
#pragma unroll
    for (int o = 16; o > 0; o >>= 1) v += __shfl_down_sync(0xffffffffu, v, o);
    __shared__ float ws[32];
    int lane = t & 31, w = t >> 5;
    if (lane == 0) ws[w] = v;
    __syncthreads();
    if (t == 0) {
        float s = 0.0f;
#pragma unroll
        for (int i = 0; i < 32; i++) s += ws[i];
        out[PERP_OFF] = expf(-s);
        // loss = mean((zq-z)^2) + 0.25*mean((zq-z)^2)  (sg is numerically a no-op)
        float L = g_lossSum * (1.0f / 8388608.0f);
        out[0] = L + 0.25f * L;
    }
}

// ---------------------------------------------------------------------------
extern "C" void kernel_launch(void* const* d_in, const int* in_sizes, int n_in,
                              void* d_out, int out_size) {
    const float* z  = (const float*)d_in[0];
    const float* cb = (const float*)d_in[1];
    if (n_in >= 2 && in_sizes[0] == KC * DIM) {  // robustness: detect swap
        z  = (const float*)d_in[1];
        cb = (const float*)d_in[0];
    }
    float* out = (float*)d_out;

    const int SMEM_BYTES = (DIM * TM + DIM * TN + TM) * 4;  // 197120
    cudaFuncSetAttribute(argminKernel,
                         cudaFuncAttributeMaxDynamicSharedMemorySize, SMEM_BYTES);

    initKernel<<<1, 1024>>>();
    transposeCB<<<dim3(KC / 32, DIM / 32), dim3(32, 8)>>>(cb);
    codeNorms<<<KC, 256>>>(cb);
    zeroEnc<<<16384, 1024>>>(out);
    argminKernel<<<N_VEC / TM, NTHR, SMEM_BYTES>>>(z);
    zqLossKernel<<<8192, 256>>>(z, cb, out);
    scatterKernel<<<N_VEC / 1024, 1024>>>(out);
    finalizeKernel<<<1, 1024>>>(out);
}

// round 5
// speedup vs baseline: 1.3346x; 1.3346x over previous
#include <cuda_runtime.h>
#include <cuda_bf16.h>
#include <cstdint>

// Problem constants
#define N_VEC   32768
#define DIM     256
#define KC      1024
#define HW      1024

// Output layout (flattened reference tuple, float32)
#define ZQ_OFF    1
#define PERP_OFF  8388609
#define ENC_OFF   8388610
#define IDX_OFF   41943042ull

// ---------------------------------------------------------------------------
// Device scratch (no allocations allowed)
__device__ __nv_bfloat16 g_zs0[N_VEC * DIM];   // z hi   (n-major [n][c])
__device__ __nv_bfloat16 g_zs1[N_VEC * DIM];   // z mid
__device__ __nv_bfloat16 g_zs2[N_VEC * DIM];   // z lo
__device__ __nv_bfloat16 g_es0[KC * DIM];      // e hi   ([k][c])
__device__ __nv_bfloat16 g_es1[KC * DIM];      // e mid
__device__ __nv_bfloat16 g_es2[KC * DIM];      // e lo
__device__ double g_znD[N_VEC];                // ||z_n||^2 fp64
__device__ float  g_eNorm[KC];                 // fp32(||e_k||^2) fp64-acc
__device__ int4   g_cand[N_VEC];               // top-4 approx candidates
__device__ float4 g_candV[N_VEC];              // their approx scores
__device__ int    g_idx[N_VEC];
__device__ float  g_lossSum;
__device__ int    g_counts[KC];

// ---------------------------------------------------------------------------
__device__ __forceinline__ uint32_t smemU32(const void* p) {
    uint32_t a;
    asm("{ .reg .u64 t; cvta.to.shared.u64 t, %1; cvt.u32.u64 %0, t; }"
        : "=r"(a) : "l"(p));
    return a;
}
__device__ __forceinline__ void cpAsync16(uint32_t dst, const void* src) {
    asm volatile("cp.async.cg.shared.global [%0], [%1], 16;" :: "r"(dst), "l"(src));
}
#define CP_COMMIT() asm volatile("cp.async.commit_group;")
#define CP_WAIT1()  asm volatile("cp.async.wait_group 1;")
#define CP_WAIT0()  asm volatile("cp.async.wait_group 0;")

__device__ __forceinline__ uint32_t lds32(uint32_t a) {
    uint32_t v;
    asm volatile("ld.shared.b32 %0, [%1];" : "=r"(v) : "r"(a));
    return v;
}
__device__ __forceinline__ void mma16816(float* c, uint32_t a0, uint32_t a1,
                                         uint32_t a2, uint32_t a3,
                                         uint32_t b0, uint32_t b1) {
    asm volatile(
        "mma.sync.aligned.m16n8k16.row.col.f32.bf16.bf16.f32 "
        "{%0,%1,%2,%3}, {%4,%5,%6,%7}, {%8,%9}, {%0,%1,%2,%3};"
        : "+f"(c[0]), "+f"(c[1]), "+f"(c[2]), "+f"(c[3])
        : "r"(a0), "r"(a1), "r"(a2), "r"(a3), "r"(b0), "r"(b1));
}

// GEMM config
#define M_CTA   64
#define SM_A    0            // 3 limbs x 64 rows x 512B = 98304
#define SM_B    98304        // 2 bufs x (128 codes x 512B) = 131072
#define GSMEM   229376

// ---------------------------------------------------------------------------
__global__ void initKernel() {
    int i = blockIdx.x * 1024 + threadIdx.x;   // grid 32 -> 32768
    g_znD[i] = 0.0;
    if (i < KC) g_counts[i] = 0;
    if (i == 0) g_lossSum = 0.0f;
}

// Split codebook into 3 exact bf16 limbs + fp64 norms. grid KC, block 256.
__global__ void splitCB(const float* __restrict__ cb) {
    int k = blockIdx.x, c = threadIdx.x;
    float v = cb[k * DIM + c];
    __nv_bfloat16 h = __float2bfloat16_rn(v);
    float r1 = v - __bfloat162float(h);
    __nv_bfloat16 m = __float2bfloat16_rn(r1);
    float r2 = r1 - __bfloat162float(m);
    __nv_bfloat16 l = __float2bfloat16_rn(r2);
    size_t o = (size_t)k * DIM + c;
    g_es0[o] = h; g_es1[o] = m; g_es2[o] = l;

    double s = (double)v * (double)v;
#pragma unroll
    for (int off = 16; off > 0; off >>= 1) s += __shfl_down_sync(0xffffffffu, s, off);
    __shared__ double ws[8];
    int lane = c & 31, w = c >> 5;
    if (lane == 0) ws[w] = s;
    __syncthreads();
    if (c == 0) {
        double t = 0.0;
#pragma unroll
        for (int i = 0; i < 8; i++) t += ws[i];
        g_eNorm[k] = (float)t;
    }
}

// Split z (NCHW) into 3 exact bf16 limbs in n-major [n][c] + fp64 ||z_n||^2.
__global__ void splitZ(const float* __restrict__ z) {
    __shared__ float tile[32][33];
    __shared__ double colsum[32][8];
    int x = threadIdx.x & 31, y = threadIdx.x >> 5;
    int hw0 = blockIdx.x * 32, c0 = blockIdx.y * 32, b = blockIdx.z;
    const float* p = z + ((size_t)b * DIM + c0) * HW + hw0;
    double s = 0.0;
#pragma unroll
    for (int i = 0; i < 32; i += 8) {
        float v = p[(size_t)(y + i) * HW + x];
        tile[y + i][x] = v;
        s += (double)v * (double)v;
    }
    colsum[x][y] = s;
    __syncthreads();
    if (y == 0) {
        double t = 0.0;
#pragma unroll
        for (int j = 0; j < 8; j++) t += colsum[x][j];
        atomicAdd(&g_znD[b * HW + hw0 + x], t);
    }
#pragma unroll
    for (int i = 0; i < 32; i += 8) {
        float v = tile[x][y + i];               // c = c0+x, n = b*HW+hw0+y+i
        __nv_bfloat16 h = __float2bfloat16_rn(v);
        float r1 = v - __bfloat162float(h);
        __nv_bfloat16 m = __float2bfloat16_rn(r1);
        float r2 = r1 - __bfloat162float(m);
        __nv_bfloat16 l = __float2bfloat16_rn(r2);
        size_t o = (size_t)(b * HW + hw0 + y + i) * DIM + c0 + x;
        g_zs0[o] = h; g_zs1[o] = m; g_zs2[o] = l;
    }
}

// ---------------------------------------------------------------------------
__device__ __forceinline__ void loadB(uint32_t sb, int chunk, int el, int buf,
                                      int tid) {
    const __nv_bfloat16* src = (el == 0) ? g_es0 : (el == 1) ? g_es1 : g_es2;
    uint32_t bbase = sb + SM_B + buf * 65536;
#pragma unroll
    for (int it = 0; it < 16; it++) {
        int idx = tid + it * 256;
        int row = idx >> 5, u = idx & 31;
        const void* s = src + (size_t)(chunk * 128 + row) * DIM + u * 8;
        cpAsync16(bbase + row * 512 + ((u ^ (row & 7)) << 4), s);
    }
}

// Argmin GEMM via mma.sync m16n8k16 bf16, K_eff = 1536 (6 exact limb prods).
// Emits TOP-4 approximate candidates per vector (per-thread top-2 -> merge).
__global__ __launch_bounds__(256, 1) void gemmArgmin() {
    extern __shared__ char smem[];
    uint32_t sb = smemU32(smem);
    int tid = threadIdx.x;
    int n0 = blockIdx.x * M_CTA;
    int lane = tid & 31, wid = tid >> 5;
    int mw = wid & 3, nw = wid >> 2;       // 4 M-warps x 2 N-warps
    int gr = lane >> 2, qc = lane & 3;

    {   // load A: 3 z limbs, 64 rows x 512B each, swizzled
        const __nv_bfloat16* zsrc[3] = {g_zs0, g_zs1, g_zs2};
#pragma unroll
        for (int it = 0; it < 24; it++) {
            int idx = tid + it * 256;
            int limb = idx >> 11, rem = idx & 2047;
            int row = rem >> 5, u = rem & 31;
            const void* s = zsrc[limb] + (size_t)(n0 + row) * DIM + u * 8;
            cpAsync16(sb + SM_A + limb * 32768 + row * 512 +
                      ((u ^ (row & 7)) << 4), s);
        }
    }
    loadB(sb, 0, 0, 0, tid);
    CP_COMMIT();

    int ra = mw * 16 + gr;                 // local row (and ra+8)
    float zn0 = (float)g_znD[n0 + ra];
    float zn1 = (float)g_znD[n0 + ra + 8];
    // per-thread top-2 per row
    float b0v = 3.4e38f, b0w = 3.4e38f, b1v = 3.4e38f, b1w = 3.4e38f;
    int   b0i = 0, b0j = 0, b1i = 0, b1j = 0;

    float acc[8][4];
#pragma unroll
    for (int i = 0; i < 8; i++)
#pragma unroll
        for (int j = 0; j < 4; j++) acc[i][j] = 0.0f;

    uint32_t aRow0 = sb + SM_A + ra * 512 + qc * 4;
    uint32_t aRow1 = sb + SM_A + (ra + 8) * 512 + qc * 4;
    int aswz = ra & 7;

    for (int s = 0; s < 24; s++) {
        int chunk = s / 3, el = s % 3, buf = s & 1;
        if (s + 1 < 24) {
            loadB(sb, (s + 1) / 3, (s + 1) % 3, buf ^ 1, tid);
            CP_COMMIT();
            CP_WAIT1();
        } else {
            CP_WAIT0();
        }
        __syncthreads();

        uint32_t bbase = sb + SM_B + buf * 65536;
        int nz = 3 - el;
        for (int zl = 0; zl < nz; zl++) {
            uint32_t a0r = aRow0 + zl * 32768;
            uint32_t a1r = aRow1 + zl * 32768;
#pragma unroll 2
            for (int ks = 0; ks < 16; ks++) {
                int ku = ks * 2;
                uint32_t a0 = lds32(a0r + ((ku ^ aswz) << 4));
                uint32_t a1 = lds32(a1r + ((ku ^ aswz) << 4));
                uint32_t a2 = lds32(a0r + (((ku + 1) ^ aswz) << 4));
                uint32_t a3 = lds32(a1r + (((ku + 1) ^ aswz) << 4));
#pragma unroll
                for (int blk = 0; blk < 8; blk++) {
                    int n = nw * 64 + blk * 8 + gr;
                    uint32_t nb = bbase + n * 512 + qc * 4;
                    int nswz = n & 7;
                    uint32_t b0 = lds32(nb + ((ku ^ nswz) << 4));
                    uint32_t b1 = lds32(nb + (((ku + 1) ^ nswz) << 4));
                    mma16816(acc[blk], a0, a1, a2, a3, b0, b1);
                }
            }
        }

        if (el == 2) {   // chunk complete: score + running top-2, zero acc
#pragma unroll
            for (int blk = 0; blk < 8; blk++) {
                int c = chunk * 128 + nw * 64 + blk * 8 + qc * 2;
                float en0 = __ldg(&g_eNorm[c]);
                float en1 = __ldg(&g_eNorm[c + 1]);
                float v;
                v = __fsub_rn(__fadd_rn(zn0, en0), 2.0f * acc[blk][0]);
                if (v < b0v) { b0w = b0v; b0j = b0i; b0v = v; b0i = c; }
                else if (v < b0w) { b0w = v; b0j = c; }
                v = __fsub_rn(__fadd_rn(zn0, en1), 2.0f * acc[blk][1]);
                if (v < b0v) { b0w = b0v; b0j = b0i; b0v = v; b0i = c + 1; }
                else if (v < b0w) { b0w = v; b0j = c + 1; }
                v = __fsub_rn(__fadd_rn(zn1, en0), 2.0f * acc[blk][2]);
                if (v < b1v) { b1w = b1v; b1j = b1i; b1v = v; b1i = c; }
                else if (v < b1w) { b1w = v; b1j = c; }
                v = __fsub_rn(__fadd_rn(zn1, en1), 2.0f * acc[blk][3]);
                if (v < b1v) { b1w = b1v; b1j = b1i; b1v = v; b1i = c + 1; }
                else if (v < b1w) { b1w = v; b1j = c + 1; }
                acc[blk][0] = acc[blk][1] = acc[blk][2] = acc[blk][3] = 0.0f;
            }
        }
        __syncthreads();
    }

    // cross-thread merge: 16 (val,idx) pairs per row -> top-4
    float* redV = (float*)(smem + SM_B);                 // 64 x 16
    int*   redI = (int*)(smem + SM_B + 64 * 16 * 4);
    int slot = (nw * 4 + qc) * 2;
    redV[ra * 16 + slot] = b0v;           redI[ra * 16 + slot] = b0i;
    redV[ra * 16 + slot + 1] = b0w;       redI[ra * 16 + slot + 1] = b0j;
    redV[(ra + 8) * 16 + slot] = b1v;     redI[(ra + 8) * 16 + slot] = b1i;
    redV[(ra + 8) * 16 + slot + 1] = b1w; redI[(ra + 8) * 16 + slot + 1] = b1j;
    __syncthreads();
    if (tid < M_CTA) {
        float v[16]; int ix[16];
#pragma unroll
        for (int t = 0; t < 16; t++) {
            v[t] = redV[tid * 16 + t];
            ix[t] = redI[tid * 16 + t];
        }
        float cv[4]; int ci[4];
#pragma unroll
        for (int s = 0; s < 4; s++) {
            float bv = 3.4e38f; int bi = 0x7fffffff; int bp = 0;
#pragma unroll
            for (int t = 0; t < 16; t++) {
                if (v[t] < bv || (v[t] == bv && ix[t] < bi)) {
                    bv = v[t]; bi = ix[t]; bp = t;
                }
            }
            cv[s] = bv; ci[s] = bi;
            v[bp] = 3.4e38f; ix[bp] = 0x7fffffff;
        }
        g_cand[n0 + tid]  = make_int4(ci[0], ci[1], ci[2], ci[3]);
        g_candV[n0 + tid] = make_float4(cv[0], cv[1], cv[2], cv[3]);
    }
}

// ---------------------------------------------------------------------------
// Refine: one warp per vector. If approx top-2 gap is wide, the HMMA winner
// is provably the reference winner. Otherwise recompute the <=4 candidate
// dots in fp64 (z from limbs, err ~2e-9) and replay the exact fp32 score
// sequence with lowest-index tie-break.
__global__ void refineKernel(const float* __restrict__ cb) {
    int lane = threadIdx.x & 31, w = threadIdx.x >> 5;
    int n = blockIdx.x * 8 + w;
    int4   cd = g_cand[n];
    float4 cv = g_candV[n];
    if (cv.y - cv.x >= 1e-4f) {
        if (lane == 0) g_idx[n] = cd.x;
        return;
    }
    // reconstruct z[c] (8 dims per lane, contiguous c = lane*8..)
    double zc[8];
    {
        uint4 u0 = ((const uint4*)(g_zs0 + (size_t)n * DIM))[lane];
        uint4 u1 = ((const uint4*)(g_zs1 + (size_t)n * DIM))[lane];
        uint4 u2 = ((const uint4*)(g_zs2 + (size_t)n * DIM))[lane];
        const uint32_t* w0 = &u0.x;
        const uint32_t* w1 = &u1.x;
        const uint32_t* w2 = &u2.x;
#pragma unroll
        for (int q = 0; q < 4; q++) {
            float2 f0 = __bfloat1622float2(*(const __nv_bfloat162*)&w0[q]);
            float2 f1 = __bfloat1622float2(*(const __nv_bfloat162*)&w1[q]);
            float2 f2 = __bfloat1622float2(*(const __nv_bfloat162*)&w2[q]);
            zc[q * 2]     = (double)f0.x + (double)f1.x + (double)f2.x;
            zc[q * 2 + 1] = (double)f0.y + (double)f1.y + (double)f2.y;
        }
    }
    float zn = (float)g_znD[n];
    float bs = 3.4e38f; int bi = 0x7fffffff;
    const int* kk = &cd.x;
#pragma unroll
    for (int j = 0; j < 4; j++) {
        int k = kk[j];
        const float4* crow = (const float4*)(cb + (size_t)k * DIM);
        float4 e0 = __ldg(&crow[lane * 2]);
        float4 e1 = __ldg(&crow[lane * 2 + 1]);
        double acc = zc[0] * (double)e0.x + zc[1] * (double)e0.y
                   + zc[2] * (double)e0.z + zc[3] * (double)e0.w
                   + zc[4] * (double)e1.x + zc[5] * (double)e1.y
                   + zc[6] * (double)e1.z + zc[7] * (double)e1.w;
#pragma unroll
        for (int o = 16; o > 0; o >>= 1)
            acc += __shfl_down_sync(0xffffffffu, acc, o);
        if (lane == 0) {
            float s = __fsub_rn(__fadd_rn(zn, __ldg(&g_eNorm[k])),
                                2.0f * (float)acc);
            if (s < bs || (s == bs && k < bi)) { bs = s; bi = k; }
        }
    }
    if (lane == 0) g_idx[n] = bi;
}

// ---------------------------------------------------------------------------
__global__ void zqLossKernel(const float* __restrict__ z,
                             const float* __restrict__ cb,
                             float* __restrict__ out) {
    int i4 = blockIdx.x * blockDim.x + threadIdx.x;
    float4 zv = ((const float4*)z)[i4];
    int base = i4 << 2;
    int hw = base & (HW - 1);
    int c  = (base >> 10) & (DIM - 1);
    int b  = base >> 18;
    int n  = b * HW + hw;
    float zz[4] = {zv.x, zv.y, zv.z, zv.w};
    float ls = 0.0f;
#pragma unroll
    for (int j = 0; j < 4; j++) {
        int k = g_idx[n + j];
        float q = __ldg(cb + k * DIM + c);
        float d = q - zz[j];
        out[ZQ_OFF + base + j] = zz[j] + d;
        ls += d * d;
    }
#pragma unroll
    for (int o = 16; o > 0; o >>= 1) ls += __shfl_down_sync(0xffffffffu, ls, o);
    __shared__ float ws[8];
    int lane = threadIdx.x & 31, w = threadIdx.x >> 5;
    if (lane == 0) ws[w] = ls;
    __syncthreads();
    if (threadIdx.x == 0) {
        float t = 0.0f;
#pragma unroll
        for (int i = 0; i < 8; i++) t += ws[i];
        atomicAdd(&g_lossSum, t);
    }
}

// Fused one-hot write (full rows, pure streaming) + indices + histogram
__global__ void onehotKernel(float* __restrict__ out) {
    int n = blockIdx.x;
    int k = g_idx[n];
    size_t base = ENC_OFF + (size_t)n * KC;
    int t = threadIdx.x;   // 256
#pragma unroll
    for (int q = 0; q < 2; q++) {
        int c2 = t + q * 256;
        float2 v = make_float2(0.0f, 0.0f);
        if (k == 2 * c2)     v.x = 1.0f;
        if (k == 2 * c2 + 1) v.y = 1.0f;
        *(float2*)(out + base + 2 * c2) = v;
    }
    if (t == 0) {
        out[IDX_OFF + n] = (float)k;
        atomicAdd(&g_counts[k], 1);
    }
}

__global__ void finalizeKernel(float* __restrict__ out) {
    int t = threadIdx.x;   // 1024
    float em = (float)g_counts[t] * (1.0f / (float)N_VEC);
    float v = em * logf(em + 1e-10f);
#pragma unroll
    for (int o = 16; o > 0; o >>= 1) v += __shfl_down_sync(0xffffffffu, v, o);
    __shared__ float ws[32];
    int lane = t & 31, w = t >> 5;
    if (lane == 0) ws[w] = v;
    __syncthreads();
    if (t == 0) {
        float s = 0.0f;
#pragma unroll
        for (int i = 0; i < 32; i++) s += ws[i];
        out[PERP_OFF] = expf(-s);
        float L = g_lossSum * (1.0f / 8388608.0f);
        out[0] = L + 0.25f * L;
    }
}

// ---------------------------------------------------------------------------
extern "C" void kernel_launch(void* const* d_in, const int* in_sizes, int n_in,
                              void* d_out, int out_size) {
    const float* z  = (const float*)d_in[0];
    const float* cb = (const float*)d_in[1];
    if (n_in >= 2 && in_sizes[0] == KC * DIM) {
        z  = (const float*)d_in[1];
        cb = (const float*)d_in[0];
    }
    float* out = (float*)d_out;

    cudaFuncSetAttribute(gemmArgmin,
                         cudaFuncAttributeMaxDynamicSharedMemorySize, GSMEM);

    initKernel<<<32, 1024>>>();
    splitCB<<<KC, 256>>>(cb);
    splitZ<<<dim3(32, 8, 32), 256>>>(z);
    gemmArgmin<<<N_VEC / M_CTA, 256, GSMEM>>>();
    refineKernel<<<N_VEC / 8, 256>>>(cb);
    zqLossKernel<<<8192, 256>>>(z, cb, out);
    onehotKernel<<<N_VEC, 256>>>(out);
    finalizeKernel<<<1, 1024>>>(out);
}

// round 6
// speedup vs baseline: 1.3668x; 1.0242x over previous
#include <cuda_runtime.h>
#include <cuda_bf16.h>
#include <cstdint>

// Problem constants
#define N_VEC   32768
#define DIM     256
#define KC      1024
#define HW      1024

// Output layout (flattened reference tuple, float32)
#define ZQ_OFF    1
#define PERP_OFF  8388609
#define ENC_OFF   8388610
#define IDX_OFF   41943042ull

// ---------------------------------------------------------------------------
// Device scratch (no allocations allowed)
__device__ __nv_bfloat16 g_zs0[N_VEC * DIM];   // z hi   (n-major [n][c])
__device__ __nv_bfloat16 g_zs1[N_VEC * DIM];   // z mid
__device__ __nv_bfloat16 g_zs2[N_VEC * DIM];   // z lo
__device__ __nv_bfloat16 g_es0[KC * DIM];      // e hi   ([k][c])
__device__ __nv_bfloat16 g_es1[KC * DIM];      // e mid
__device__ __nv_bfloat16 g_es2[KC * DIM];      // e lo
__device__ double g_znD[N_VEC];                // ||z_n||^2 fp64
__device__ float  g_eNorm[KC];                 // fp32(||e_k||^2) fp64-acc
__device__ int4   g_cand[N_VEC];               // top-4 approx candidates
__device__ float4 g_candV[N_VEC];              // their approx scores
__device__ int    g_idx[N_VEC];
__device__ float  g_lossSum;
__device__ int    g_counts[KC];

// ---------------------------------------------------------------------------
__device__ __forceinline__ uint32_t smemU32(const void* p) {
    uint32_t a;
    asm("{ .reg .u64 t; cvta.to.shared.u64 t, %1; cvt.u32.u64 %0, t; }"
        : "=r"(a) : "l"(p));
    return a;
}
__device__ __forceinline__ void cpAsync16(uint32_t dst, const void* src) {
    asm volatile("cp.async.cg.shared.global [%0], [%1], 16;" :: "r"(dst), "l"(src));
}
#define CP_COMMIT() asm volatile("cp.async.commit_group;")
#define CP_WAIT1()  asm volatile("cp.async.wait_group 1;")
#define CP_WAIT0()  asm volatile("cp.async.wait_group 0;")

__device__ __forceinline__ void ldsm4(uint32_t& r0, uint32_t& r1,
                                      uint32_t& r2, uint32_t& r3, uint32_t a) {
    asm volatile("ldmatrix.sync.aligned.m8n8.x4.shared.b16 {%0,%1,%2,%3}, [%4];"
                 : "=r"(r0), "=r"(r1), "=r"(r2), "=r"(r3) : "r"(a));
}
__device__ __forceinline__ void mma16816(float* c, uint32_t a0, uint32_t a1,
                                         uint32_t a2, uint32_t a3,
                                         uint32_t b0, uint32_t b1) {
    asm volatile(
        "mma.sync.aligned.m16n8k16.row.col.f32.bf16.bf16.f32 "
        "{%0,%1,%2,%3}, {%4,%5,%6,%7}, {%8,%9}, {%0,%1,%2,%3};"
        : "+f"(c[0]), "+f"(c[1]), "+f"(c[2]), "+f"(c[3])
        : "r"(a0), "r"(a1), "r"(a2), "r"(a3), "r"(b0), "r"(b1));
}

// GEMM config
#define M_CTA   64
#define SM_A    0            // 3 limbs x 64 rows x 512B = 98304
#define SM_B    98304        // 2 bufs x (128 codes x 512B) = 131072
#define GSMEM   229376

// ---------------------------------------------------------------------------
__global__ void initKernel() {
    int i = blockIdx.x * 1024 + threadIdx.x;   // grid 32 -> 32768
    g_znD[i] = 0.0;
    if (i < KC) g_counts[i] = 0;
    if (i == 0) g_lossSum = 0.0f;
}

// Split codebook into 3 exact bf16 limbs + fp64 norms. grid KC, block 256.
__global__ void splitCB(const float* __restrict__ cb) {
    int k = blockIdx.x, c = threadIdx.x;
    float v = cb[k * DIM + c];
    __nv_bfloat16 h = __float2bfloat16_rn(v);
    float r1 = v - __bfloat162float(h);
    __nv_bfloat16 m = __float2bfloat16_rn(r1);
    float r2 = r1 - __bfloat162float(m);
    __nv_bfloat16 l = __float2bfloat16_rn(r2);
    size_t o = (size_t)k * DIM + c;
    g_es0[o] = h; g_es1[o] = m; g_es2[o] = l;

    double s = (double)v * (double)v;
#pragma unroll
    for (int off = 16; off > 0; off >>= 1) s += __shfl_down_sync(0xffffffffu, s, off);
    __shared__ double ws[8];
    int lane = c & 31, w = c >> 5;
    if (lane == 0) ws[w] = s;
    __syncthreads();
    if (c == 0) {
        double t = 0.0;
#pragma unroll
        for (int i = 0; i < 8; i++) t += ws[i];
        g_eNorm[k] = (float)t;
    }
}

// Split z (NCHW) into 3 exact bf16 limbs in n-major [n][c] + fp64 ||z_n||^2.
__global__ void splitZ(const float* __restrict__ z) {
    __shared__ float tile[32][33];
    __shared__ double colsum[32][8];
    int x = threadIdx.x & 31, y = threadIdx.x >> 5;
    int hw0 = blockIdx.x * 32, c0 = blockIdx.y * 32, b = blockIdx.z;
    const float* p = z + ((size_t)b * DIM + c0) * HW + hw0;
    double s = 0.0;
#pragma unroll
    for (int i = 0; i < 32; i += 8) {
        float v = p[(size_t)(y + i) * HW + x];
        tile[y + i][x] = v;
        s += (double)v * (double)v;
    }
    colsum[x][y] = s;
    __syncthreads();
    if (y == 0) {
        double t = 0.0;
#pragma unroll
        for (int j = 0; j < 8; j++) t += colsum[x][j];
        atomicAdd(&g_znD[b * HW + hw0 + x], t);
    }
#pragma unroll
    for (int i = 0; i < 32; i += 8) {
        float v = tile[x][y + i];               // c = c0+x, n = b*HW+hw0+y+i
        __nv_bfloat16 h = __float2bfloat16_rn(v);
        float r1 = v - __bfloat162float(h);
        __nv_bfloat16 m = __float2bfloat16_rn(r1);
        float r2 = r1 - __bfloat162float(m);
        __nv_bfloat16 l = __float2bfloat16_rn(r2);
        size_t o = (size_t)(b * HW + hw0 + y + i) * DIM + c0 + x;
        g_zs0[o] = h; g_zs1[o] = m; g_zs2[o] = l;
    }
}

// ---------------------------------------------------------------------------
__device__ __forceinline__ void loadB(uint32_t sb, int chunk, int el, int buf,
                                      int tid) {
    const __nv_bfloat16* src = (el == 0) ? g_es0 : (el == 1) ? g_es1 : g_es2;
    uint32_t bbase = sb + SM_B + buf * 65536;
#pragma unroll
    for (int it = 0; it < 16; it++) {
        int idx = tid + it * 256;
        int row = idx >> 5, u = idx & 31;
        const void* s = src + (size_t)(chunk * 128 + row) * DIM + u * 8;
        cpAsync16(bbase + row * 512 + ((u ^ (row & 7)) << 4), s);
    }
}

// Argmin GEMM via mma.sync m16n8k16 bf16, K_eff = 1536 (6 exact limb prods).
// Warp tile m32 x n32 with ldmatrix.x4 fragment loads (4 LDSM + 8 HMMA per
// k16 step). Emits TOP-4 approximate candidates per vector.
__global__ __launch_bounds__(256, 1) void gemmArgmin() {
    extern __shared__ char smem[];
    uint32_t sb = smemU32(smem);
    int tid = threadIdx.x;
    int n0 = blockIdx.x * M_CTA;
    int lane = tid & 31, wid = tid >> 5;
    int mw = wid & 1, nw = wid >> 1;       // 2 M-warps x 4 N-warps
    int gr = lane >> 2, qc = lane & 3;
    int hi = lane >> 4, swz = lane & 7;
    int l15 = lane & 15;

    {   // load A: 3 z limbs, 64 rows x 512B each, swizzled
        const __nv_bfloat16* zsrc[3] = {g_zs0, g_zs1, g_zs2};
#pragma unroll
        for (int it = 0; it < 24; it++) {
            int idx = tid + it * 256;
            int limb = idx >> 11, rem = idx & 2047;
            int row = rem >> 5, u = rem & 31;
            const void* s = zsrc[limb] + (size_t)(n0 + row) * DIM + u * 8;
            cpAsync16(sb + SM_A + limb * 32768 + row * 512 +
                      ((u ^ (row & 7)) << 4), s);
        }
    }
    loadB(sb, 0, 0, 0, tid);
    CP_COMMIT();

    // rows handled by this thread: mw*32 + gr + {0,8,16,24}
    float zn[4];
#pragma unroll
    for (int ri = 0; ri < 4; ri++)
        zn[ri] = (float)g_znD[n0 + mw * 32 + gr + ri * 8];
    float bv[4], bw[4];
    int   bi[4], bj[4];
#pragma unroll
    for (int ri = 0; ri < 4; ri++) {
        bv[ri] = 3.4e38f; bw[ri] = 3.4e38f; bi[ri] = 0; bj[ri] = 0;
    }

    float acc[8][4];
#pragma unroll
    for (int i = 0; i < 8; i++)
#pragma unroll
        for (int j = 0; j < 4; j++) acc[i][j] = 0.0f;

    // ldmatrix base addresses (offset term ((2ks+hi)^swz)<<4 added per step)
    uint32_t aAddr = sb + SM_A + (mw * 32 + l15) * 512;   // + limb*32768, +8192 for mi=1
    uint32_t bRow  = (nw * 32 + l15) * 512;               // + bbase, +8192 for half=1

    for (int s = 0; s < 24; s++) {
        int chunk = s / 3, el = s % 3, buf = s & 1;
        if (s + 1 < 24) {
            loadB(sb, (s + 1) / 3, (s + 1) % 3, buf ^ 1, tid);
            CP_COMMIT();
            CP_WAIT1();
        } else {
            CP_WAIT0();
        }
        __syncthreads();

        uint32_t bb = sb + SM_B + buf * 65536 + bRow;
        int nz = 3 - el;
        for (int zl = 0; zl < nz; zl++) {
            uint32_t aa = aAddr + zl * 32768;
#pragma unroll 4
            for (int ks = 0; ks < 16; ks++) {
                uint32_t off = (uint32_t)(((2 * ks + hi) ^ swz) << 4);
                uint32_t a0, a1, a2, a3, a4, a5, a6, a7;
                uint32_t b0, b1, b2, b3, b4, b5, b6, b7;
                ldsm4(a0, a1, a2, a3, aa + off);            // m16 tile 0
                ldsm4(a4, a5, a6, a7, aa + 8192 + off);     // m16 tile 1
                ldsm4(b0, b1, b2, b3, bb + off);            // n16 half 0
                ldsm4(b4, b5, b6, b7, bb + 8192 + off);     // n16 half 1
                mma16816(acc[0], a0, a1, a2, a3, b0, b2);   // n blk 0
                mma16816(acc[1], a0, a1, a2, a3, b1, b3);   // n blk 1
                mma16816(acc[2], a0, a1, a2, a3, b4, b6);   // n blk 2
                mma16816(acc[3], a0, a1, a2, a3, b5, b7);   // n blk 3
                mma16816(acc[4], a4, a5, a6, a7, b0, b2);
                mma16816(acc[5], a4, a5, a6, a7, b1, b3);
                mma16816(acc[6], a4, a5, a6, a7, b4, b6);
                mma16816(acc[7], a4, a5, a6, a7, b5, b7);
            }
        }

        if (el == 2) {   // chunk complete: score + running top-2, zero acc
#pragma unroll
            for (int mi = 0; mi < 2; mi++)
#pragma unroll
            for (int blk = 0; blk < 4; blk++) {
                int i = mi * 4 + blk;
                int c = chunk * 128 + nw * 32 + blk * 8 + qc * 2;
                float en0 = __ldg(&g_eNorm[c]);
                float en1 = __ldg(&g_eNorm[c + 1]);
                int r0 = mi * 2, r1 = mi * 2 + 1;
                float v;
                v = __fsub_rn(__fadd_rn(zn[r0], en0), 2.0f * acc[i][0]);
                if (v < bv[r0]) { bw[r0] = bv[r0]; bj[r0] = bi[r0]; bv[r0] = v; bi[r0] = c; }
                else if (v < bw[r0]) { bw[r0] = v; bj[r0] = c; }
                v = __fsub_rn(__fadd_rn(zn[r0], en1), 2.0f * acc[i][1]);
                if (v < bv[r0]) { bw[r0] = bv[r0]; bj[r0] = bi[r0]; bv[r0] = v; bi[r0] = c + 1; }
                else if (v < bw[r0]) { bw[r0] = v; bj[r0] = c + 1; }
                v = __fsub_rn(__fadd_rn(zn[r1], en0), 2.0f * acc[i][2]);
                if (v < bv[r1]) { bw[r1] = bv[r1]; bj[r1] = bi[r1]; bv[r1] = v; bi[r1] = c; }
                else if (v < bw[r1]) { bw[r1] = v; bj[r1] = c; }
                v = __fsub_rn(__fadd_rn(zn[r1], en1), 2.0f * acc[i][3]);
                if (v < bv[r1]) { bw[r1] = bv[r1]; bj[r1] = bi[r1]; bv[r1] = v; bi[r1] = c + 1; }
                else if (v < bw[r1]) { bw[r1] = v; bj[r1] = c + 1; }
                acc[i][0] = acc[i][1] = acc[i][2] = acc[i][3] = 0.0f;
            }
        }
        __syncthreads();
    }

    // cross-thread merge: 32 (val,idx) pairs per row -> top-4
    float* redV = (float*)(smem + SM_B);                 // 64 rows x 32
    int*   redI = (int*)(smem + SM_B + 64 * 32 * 4);
    int slot = (nw * 4 + qc) * 2;
#pragma unroll
    for (int ri = 0; ri < 4; ri++) {
        int row = mw * 32 + gr + ri * 8;
        redV[row * 32 + slot] = bv[ri];     redI[row * 32 + slot] = bi[ri];
        redV[row * 32 + slot + 1] = bw[ri]; redI[row * 32 + slot + 1] = bj[ri];
    }
    __syncthreads();
    if (tid < M_CTA) {
        float v[32]; int ix[32];
#pragma unroll
        for (int t = 0; t < 32; t++) {
            v[t] = redV[tid * 32 + t];
            ix[t] = redI[tid * 32 + t];
        }
        float cv[4]; int ci[4];
#pragma unroll
        for (int s = 0; s < 4; s++) {
            float bvv = 3.4e38f; int bii = 0x7fffffff; int bp = 0;
#pragma unroll
            for (int t = 0; t < 32; t++) {
                if (v[t] < bvv || (v[t] == bvv && ix[t] < bii)) {
                    bvv = v[t]; bii = ix[t]; bp = t;
                }
            }
            cv[s] = bvv; ci[s] = bii;
            v[bp] = 3.4e38f; ix[bp] = 0x7fffffff;
        }
        g_cand[n0 + tid]  = make_int4(ci[0], ci[1], ci[2], ci[3]);
        g_candV[n0 + tid] = make_float4(cv[0], cv[1], cv[2], cv[3]);
    }
}

// ---------------------------------------------------------------------------
// Refine: one warp per vector. Wide approx top-2 gap -> HMMA winner provably
// the reference winner; else recompute <=4 candidate dots in fp64 and replay
// the exact fp32 score sequence with lowest-index tie-break.
__global__ void refineKernel(const float* __restrict__ cb) {
    int lane = threadIdx.x & 31, w = threadIdx.x >> 5;
    int n = blockIdx.x * 8 + w;
    int4   cd = g_cand[n];
    float4 cv = g_candV[n];
    if (cv.y - cv.x >= 1e-4f) {
        if (lane == 0) g_idx[n] = cd.x;
        return;
    }
    double zc[8];
    {
        uint4 u0 = ((const uint4*)(g_zs0 + (size_t)n * DIM))[lane];
        uint4 u1 = ((const uint4*)(g_zs1 + (size_t)n * DIM))[lane];
        uint4 u2 = ((const uint4*)(g_zs2 + (size_t)n * DIM))[lane];
        const uint32_t* w0 = &u0.x;
        const uint32_t* w1 = &u1.x;
        const uint32_t* w2 = &u2.x;
#pragma unroll
        for (int q = 0; q < 4; q++) {
            float2 f0 = __bfloat1622float2(*(const __nv_bfloat162*)&w0[q]);
            float2 f1 = __bfloat1622float2(*(const __nv_bfloat162*)&w1[q]);
            float2 f2 = __bfloat1622float2(*(const __nv_bfloat162*)&w2[q]);
            zc[q * 2]     = (double)f0.x + (double)f1.x + (double)f2.x;
            zc[q * 2 + 1] = (double)f0.y + (double)f1.y + (double)f2.y;
        }
    }
    float zn = (float)g_znD[n];
    float bs = 3.4e38f; int bi = 0x7fffffff;
    const int* kk = &cd.x;
#pragma unroll
    for (int j = 0; j < 4; j++) {
        int k = kk[j];
        const float4* crow = (const float4*)(cb + (size_t)k * DIM);
        float4 e0 = __ldg(&crow[lane * 2]);
        float4 e1 = __ldg(&crow[lane * 2 + 1]);
        double acc = zc[0] * (double)e0.x + zc[1] * (double)e0.y
                   + zc[2] * (double)e0.z + zc[3] * (double)e0.w
                   + zc[4] * (double)e1.x + zc[5] * (double)e1.y
                   + zc[6] * (double)e1.z + zc[7] * (double)e1.w;
#pragma unroll
        for (int o = 16; o > 0; o >>= 1)
            acc += __shfl_down_sync(0xffffffffu, acc, o);
        if (lane == 0) {
            float s = __fsub_rn(__fadd_rn(zn, __ldg(&g_eNorm[k])),
                                2.0f * (float)acc);
            if (s < bs || (s == bs && k < bi)) { bs = s; bi = k; }
        }
    }
    if (lane == 0) g_idx[n] = bi;
}

// ---------------------------------------------------------------------------
__global__ void zqLossKernel(const float* __restrict__ z,
                             const float* __restrict__ cb,
                             float* __restrict__ out) {
    int i4 = blockIdx.x * blockDim.x + threadIdx.x;
    float4 zv = ((const float4*)z)[i4];
    int base = i4 << 2;
    int hw = base & (HW - 1);
    int c  = (base >> 10) & (DIM - 1);
    int b  = base >> 18;
    int n  = b * HW + hw;
    float zz[4] = {zv.x, zv.y, zv.z, zv.w};
    float ls = 0.0f;
#pragma unroll
    for (int j = 0; j < 4; j++) {
        int k = g_idx[n + j];
        float q = __ldg(cb + k * DIM + c);
        float d = q - zz[j];
        out[ZQ_OFF + base + j] = zz[j] + d;
        ls += d * d;
    }
#pragma unroll
    for (int o = 16; o > 0; o >>= 1) ls += __shfl_down_sync(0xffffffffu, ls, o);
    __shared__ float ws[8];
    int lane = threadIdx.x & 31, w = threadIdx.x >> 5;
    if (lane == 0) ws[w] = ls;
    __syncthreads();
    if (threadIdx.x == 0) {
        float t = 0.0f;
#pragma unroll
        for (int i = 0; i < 8; i++) t += ws[i];
        atomicAdd(&g_lossSum, t);
    }
}

// Fused one-hot write (full rows, pure streaming) + indices + histogram
__global__ void onehotKernel(float* __restrict__ out) {
    int n = blockIdx.x;
    int k = g_idx[n];
    size_t base = ENC_OFF + (size_t)n * KC;
    int t = threadIdx.x;   // 256
#pragma unroll
    for (int q = 0; q < 2; q++) {
        int c2 = t + q * 256;
        float2 v = make_float2(0.0f, 0.0f);
        if (k == 2 * c2)     v.x = 1.0f;
        if (k == 2 * c2 + 1) v.y = 1.0f;
        *(float2*)(out + base + 2 * c2) = v;
    }
    if (t == 0) {
        out[IDX_OFF + n] = (float)k;
        atomicAdd(&g_counts[k], 1);
    }
}

__global__ void finalizeKernel(float* __restrict__ out) {
    int t = threadIdx.x;   // 1024
    float em = (float)g_counts[t] * (1.0f / (float)N_VEC);
    float v = em * logf(em + 1e-10f);
#pragma unroll
    for (int o = 16; o > 0; o >>= 1) v += __shfl_down_sync(0xffffffffu, v, o);
    __shared__ float ws[32];
    int lane = t & 31, w = t >> 5;
    if (lane == 0) ws[w] = v;
    __syncthreads();
    if (t == 0) {
        float s = 0.0f;
#pragma unroll
        for (int i = 0; i < 32; i++) s += ws[i];
        out[PERP_OFF] = expf(-s);
        float L = g_lossSum * (1.0f / 8388608.0f);
        out[0] = L + 0.25f * L;
    }
}

// ---------------------------------------------------------------------------
extern "C" void kernel_launch(void* const* d_in, const int* in_sizes, int n_in,
                              void* d_out, int out_size) {
    const float* z  = (const float*)d_in[0];
    const float* cb = (const float*)d_in[1];
    if (n_in >= 2 && in_sizes[0] == KC * DIM) {
        z  = (const float*)d_in[1];
        cb = (const float*)d_in[0];
    }
    float* out = (float*)d_out;

    cudaFuncSetAttribute(gemmArgmin,
                         cudaFuncAttributeMaxDynamicSharedMemorySize, GSMEM);

    initKernel<<<32, 1024>>>();
    splitCB<<<KC, 256>>>(cb);
    splitZ<<<dim3(32, 8, 32), 256>>>(z);
    gemmArgmin<<<N_VEC / M_CTA, 256, GSMEM>>>();
    refineKernel<<<N_VEC / 8, 256>>>(cb);
    zqLossKernel<<<8192, 256>>>(z, cb, out);
    onehotKernel<<<N_VEC, 256>>>(out);
    finalizeKernel<<<1, 1024>>>(out);
}

// round 7
// speedup vs baseline: 2.0299x; 1.4851x over previous
#include <cuda_runtime.h>
#include <cuda_bf16.h>
#include <cstdint>

// Problem constants
#define N_VEC   32768
#define DIM     256
#define KC      1024
#define HW      1024

// Output layout (flattened reference tuple, float32)
#define ZQ_OFF    1
#define PERP_OFF  8388609
#define ENC_OFF   8388610
#define IDX_OFF   41943042ull

// ---------------------------------------------------------------------------
// Device scratch (no allocations allowed)
__device__ __nv_bfloat16 g_zs0[N_VEC * DIM];   // z hi   (n-major [n][c])
__device__ __nv_bfloat16 g_zs1[N_VEC * DIM];   // z mid
__device__ __nv_bfloat16 g_zs2[N_VEC * DIM];   // z lo (refine only)
__device__ __nv_bfloat16 g_es0[KC * DIM];      // e hi   ([k][c])
__device__ __nv_bfloat16 g_es1[KC * DIM];      // e mid
__device__ double g_znD[N_VEC];                // ||z_n||^2 fp64
__device__ float  g_eNorm[KC];                 // fp32(||e_k||^2) fp64-acc
__device__ int4   g_cand[N_VEC];               // top-4 approx candidates
__device__ float4 g_candV[N_VEC];              // their approx scores
__device__ int    g_idx[N_VEC];
__device__ float  g_lossSum;
__device__ int    g_counts[KC];

// ---------------------------------------------------------------------------
__device__ __forceinline__ uint32_t smemU32(const void* p) {
    uint32_t a;
    asm("{ .reg .u64 t; cvta.to.shared.u64 t, %1; cvt.u32.u64 %0, t; }"
        : "=r"(a) : "l"(p));
    return a;
}
__device__ __forceinline__ void cpAsync16(uint32_t dst, const void* src) {
    asm volatile("cp.async.cg.shared.global [%0], [%1], 16;" :: "r"(dst), "l"(src));
}
#define CP_COMMIT() asm volatile("cp.async.commit_group;")
#define CP_WAIT1()  asm volatile("cp.async.wait_group 1;")
#define CP_WAIT0()  asm volatile("cp.async.wait_group 0;")

__device__ __forceinline__ void ldsm4(uint32_t& r0, uint32_t& r1,
                                      uint32_t& r2, uint32_t& r3, uint32_t a) {
    asm volatile("ldmatrix.sync.aligned.m8n8.x4.shared.b16 {%0,%1,%2,%3}, [%4];"
                 : "=r"(r0), "=r"(r1), "=r"(r2), "=r"(r3) : "r"(a));
}
__device__ __forceinline__ void mma16816(float* c, uint32_t a0, uint32_t a1,
                                         uint32_t a2, uint32_t a3,
                                         uint32_t b0, uint32_t b1) {
    asm volatile(
        "mma.sync.aligned.m16n8k16.row.col.f32.bf16.bf16.f32 "
        "{%0,%1,%2,%3}, {%4,%5,%6,%7}, {%8,%9}, {%0,%1,%2,%3};"
        : "+f"(c[0]), "+f"(c[1]), "+f"(c[2]), "+f"(c[3])
        : "r"(a0), "r"(a1), "r"(a2), "r"(a3), "r"(b0), "r"(b1));
}

// GEMM config
#define M_CTA   64
#define SM_A    0            // 2 limbs x 64 rows x 512B = 65536
#define SM_B    65536        // 2 bufs x (128 codes x 512B) = 131072
#define GSMEM   196608

// load one m32(or n32)-wide fragment pair from swizzled smem
#define LD_T(arr, p, base, off) \
    ldsm4(arr[p][0], arr[p][1], arr[p][2], arr[p][3], (base) + (off)); \
    ldsm4(arr[p][4], arr[p][5], arr[p][6], arr[p][7], (base) + 8192 + (off));

// ---------------------------------------------------------------------------
__global__ void initKernel() {
    int i = blockIdx.x * 1024 + threadIdx.x;   // grid 32 -> 32768
    g_znD[i] = 0.0;
    if (i < KC) g_counts[i] = 0;
    if (i == 0) g_lossSum = 0.0f;
}

// Split codebook into 2 exact bf16 limbs (GEMM) + fp64 norms. grid KC, 256.
__global__ void splitCB(const float* __restrict__ cb) {
    int k = blockIdx.x, c = threadIdx.x;
    float v = cb[k * DIM + c];
    __nv_bfloat16 h = __float2bfloat16_rn(v);
    float r1 = v - __bfloat162float(h);
    __nv_bfloat16 m = __float2bfloat16_rn(r1);
    size_t o = (size_t)k * DIM + c;
    g_es0[o] = h; g_es1[o] = m;

    double s = (double)v * (double)v;
#pragma unroll
    for (int off = 16; off > 0; off >>= 1) s += __shfl_down_sync(0xffffffffu, s, off);
    __shared__ double ws[8];
    int lane = c & 31, w = c >> 5;
    if (lane == 0) ws[w] = s;
    __syncthreads();
    if (c == 0) {
        double t = 0.0;
#pragma unroll
        for (int i = 0; i < 8; i++) t += ws[i];
        g_eNorm[k] = (float)t;
    }
}

// Split z (NCHW) into 3 exact bf16 limbs in n-major [n][c] + fp64 ||z_n||^2.
__global__ void splitZ(const float* __restrict__ z) {
    __shared__ float tile[32][33];
    __shared__ double colsum[32][8];
    int x = threadIdx.x & 31, y = threadIdx.x >> 5;
    int hw0 = blockIdx.x * 32, c0 = blockIdx.y * 32, b = blockIdx.z;
    const float* p = z + ((size_t)b * DIM + c0) * HW + hw0;
    double s = 0.0;
#pragma unroll
    for (int i = 0; i < 32; i += 8) {
        float v = p[(size_t)(y + i) * HW + x];
        tile[y + i][x] = v;
        s += (double)v * (double)v;
    }
    colsum[x][y] = s;
    __syncthreads();
    if (y == 0) {
        double t = 0.0;
#pragma unroll
        for (int j = 0; j < 8; j++) t += colsum[x][j];
        atomicAdd(&g_znD[b * HW + hw0 + x], t);
    }
#pragma unroll
    for (int i = 0; i < 32; i += 8) {
        float v = tile[x][y + i];               // c = c0+x, n = b*HW+hw0+y+i
        __nv_bfloat16 h = __float2bfloat16_rn(v);
        float r1 = v - __bfloat162float(h);
        __nv_bfloat16 m = __float2bfloat16_rn(r1);
        float r2 = r1 - __bfloat162float(m);
        __nv_bfloat16 l = __float2bfloat16_rn(r2);
        size_t o = (size_t)(b * HW + hw0 + y + i) * DIM + c0 + x;
        g_zs0[o] = h; g_zs1[o] = m; g_zs2[o] = l;
    }
}

// ---------------------------------------------------------------------------
__device__ __forceinline__ void loadB(uint32_t sb, int chunk, int el, int buf,
                                      int tid) {
    const __nv_bfloat16* src = (el == 0) ? g_es0 : g_es1;
    uint32_t bbase = sb + SM_B + buf * 65536;
#pragma unroll
    for (int it = 0; it < 16; it++) {
        int idx = tid + it * 256;
        int row = idx >> 5, u = idx & 31;
        const void* s = src + (size_t)(chunk * 128 + row) * DIM + u * 8;
        cpAsync16(bbase + row * 512 + ((u ^ (row & 7)) << 4), s);
    }
}

// Argmin GEMM via mma.sync m16n8k16 bf16. 3 limb products (zh*eh, zm*eh,
// zh*em), K_eff=768 — candidate accuracy ~3e-7 << 1e-4 gap threshold; the
// exact refine stage resolves the rest. Warp tile m32 x n32, ldmatrix.x4
// fragments, register double-buffered across ksteps. Emits TOP-4 candidates.
__global__ __launch_bounds__(256, 1) void gemmArgmin() {
    extern __shared__ char smem[];
    uint32_t sb = smemU32(smem);
    int tid = threadIdx.x;
    int n0 = blockIdx.x * M_CTA;
    int lane = tid & 31, wid = tid >> 5;
    int mw = wid & 1, nw = wid >> 1;       // 2 M-warps x 4 N-warps
    int gr = lane >> 2, qc = lane & 3;
    int hi = lane >> 4, swz = lane & 7;
    int l15 = lane & 15;

    {   // load A: z limbs 0,1; 64 rows x 512B each, swizzled
        const __nv_bfloat16* zsrc[2] = {g_zs0, g_zs1};
#pragma unroll
        for (int it = 0; it < 16; it++) {
            int idx = tid + it * 256;
            int limb = idx >> 11, rem = idx & 2047;
            int row = rem >> 5, u = rem & 31;
            const void* s = zsrc[limb] + (size_t)(n0 + row) * DIM + u * 8;
            cpAsync16(sb + SM_A + limb * 32768 + row * 512 +
                      ((u ^ (row & 7)) << 4), s);
        }
    }
    loadB(sb, 0, 0, 0, tid);
    CP_COMMIT();

    // rows handled by this thread: mw*32 + gr + {0,8,16,24}
    float zn[4];
#pragma unroll
    for (int ri = 0; ri < 4; ri++)
        zn[ri] = (float)g_znD[n0 + mw * 32 + gr + ri * 8];
    float bv[4], bw[4];
    int   bi[4], bj[4];
#pragma unroll
    for (int ri = 0; ri < 4; ri++) {
        bv[ri] = 3.4e38f; bw[ri] = 3.4e38f; bi[ri] = 0; bj[ri] = 0;
    }

    float acc[8][4];
#pragma unroll
    for (int i = 0; i < 8; i++)
#pragma unroll
        for (int j = 0; j < 4; j++) acc[i][j] = 0.0f;

    uint32_t aa0 = sb + SM_A + (mw * 32 + l15) * 512;     // z limb 0
    uint32_t aa1 = aa0 + 32768;                            // z limb 1
    uint32_t bRow = (nw * 32 + l15) * 512;

    for (int s = 0; s < 16; s++) {
        int chunk = s >> 1, el = s & 1, buf = s & 1;
        if (s + 1 < 16) {
            loadB(sb, (s + 1) >> 1, (s + 1) & 1, buf ^ 1, tid);
            CP_COMMIT();
            CP_WAIT1();
        } else {
            CP_WAIT0();
        }
        __syncthreads();

        uint32_t bb = sb + SM_B + buf * 65536 + bRow;

        if (el == 0) {
            // eh stage: products zh*eh and zm*eh (16 MMAs/kstep)
            uint32_t A0[2][8], A1[2][8], Bf[2][8];
            uint32_t off0 = (uint32_t)((hi ^ swz) << 4);
            LD_T(Bf, 0, bb, off0);
            LD_T(A0, 0, aa0, off0);
            LD_T(A1, 0, aa1, off0);
#pragma unroll
            for (int ks = 0; ks < 16; ks++) {
                int cur = ks & 1, nxt = cur ^ 1;
                if (ks < 15) {
                    uint32_t off = (uint32_t)(((2 * (ks + 1) + hi) ^ swz) << 4);
                    LD_T(Bf, nxt, bb, off);
                    LD_T(A0, nxt, aa0, off);
                    LD_T(A1, nxt, aa1, off);
                }
                mma16816(acc[0], A0[cur][0], A0[cur][1], A0[cur][2], A0[cur][3], Bf[cur][0], Bf[cur][2]);
                mma16816(acc[1], A0[cur][0], A0[cur][1], A0[cur][2], A0[cur][3], Bf[cur][1], Bf[cur][3]);
                mma16816(acc[2], A0[cur][0], A0[cur][1], A0[cur][2], A0[cur][3], Bf[cur][4], Bf[cur][6]);
                mma16816(acc[3], A0[cur][0], A0[cur][1], A0[cur][2], A0[cur][3], Bf[cur][5], Bf[cur][7]);
                mma16816(acc[4], A0[cur][4], A0[cur][5], A0[cur][6], A0[cur][7], Bf[cur][0], Bf[cur][2]);
                mma16816(acc[5], A0[cur][4], A0[cur][5], A0[cur][6], A0[cur][7], Bf[cur][1], Bf[cur][3]);
                mma16816(acc[6], A0[cur][4], A0[cur][5], A0[cur][6], A0[cur][7], Bf[cur][4], Bf[cur][6]);
                mma16816(acc[7], A0[cur][4], A0[cur][5], A0[cur][6], A0[cur][7], Bf[cur][5], Bf[cur][7]);
                mma16816(acc[0], A1[cur][0], A1[cur][1], A1[cur][2], A1[cur][3], Bf[cur][0], Bf[cur][2]);
                mma16816(acc[1], A1[cur][0], A1[cur][1], A1[cur][2], A1[cur][3], Bf[cur][1], Bf[cur][3]);
                mma16816(acc[2], A1[cur][0], A1[cur][1], A1[cur][2], A1[cur][3], Bf[cur][4], Bf[cur][6]);
                mma16816(acc[3], A1[cur][0], A1[cur][1], A1[cur][2], A1[cur][3], Bf[cur][5], Bf[cur][7]);
                mma16816(acc[4], A1[cur][4], A1[cur][5], A1[cur][6], A1[cur][7], Bf[cur][0], Bf[cur][2]);
                mma16816(acc[5], A1[cur][4], A1[cur][5], A1[cur][6], A1[cur][7], Bf[cur][1], Bf[cur][3]);
                mma16816(acc[6], A1[cur][4], A1[cur][5], A1[cur][6], A1[cur][7], Bf[cur][4], Bf[cur][6]);
                mma16816(acc[7], A1[cur][4], A1[cur][5], A1[cur][6], A1[cur][7], Bf[cur][5], Bf[cur][7]);
            }
        } else {
            // em stage: product zh*em (8 MMAs/kstep)
            uint32_t A0[2][8], Bf[2][8];
            uint32_t off0 = (uint32_t)((hi ^ swz) << 4);
            LD_T(Bf, 0, bb, off0);
            LD_T(A0, 0, aa0, off0);
#pragma unroll
            for (int ks = 0; ks < 16; ks++) {
                int cur = ks & 1, nxt = cur ^ 1;
                if (ks < 15) {
                    uint32_t off = (uint32_t)(((2 * (ks + 1) + hi) ^ swz) << 4);
                    LD_T(Bf, nxt, bb, off);
                    LD_T(A0, nxt, aa0, off);
                }
                mma16816(acc[0], A0[cur][0], A0[cur][1], A0[cur][2], A0[cur][3], Bf[cur][0], Bf[cur][2]);
                mma16816(acc[1], A0[cur][0], A0[cur][1], A0[cur][2], A0[cur][3], Bf[cur][1], Bf[cur][3]);
                mma16816(acc[2], A0[cur][0], A0[cur][1], A0[cur][2], A0[cur][3], Bf[cur][4], Bf[cur][6]);
                mma16816(acc[3], A0[cur][0], A0[cur][1], A0[cur][2], A0[cur][3], Bf[cur][5], Bf[cur][7]);
                mma16816(acc[4], A0[cur][4], A0[cur][5], A0[cur][6], A0[cur][7], Bf[cur][0], Bf[cur][2]);
                mma16816(acc[5], A0[cur][4], A0[cur][5], A0[cur][6], A0[cur][7], Bf[cur][1], Bf[cur][3]);
                mma16816(acc[6], A0[cur][4], A0[cur][5], A0[cur][6], A0[cur][7], Bf[cur][4], Bf[cur][6]);
                mma16816(acc[7], A0[cur][4], A0[cur][5], A0[cur][6], A0[cur][7], Bf[cur][5], Bf[cur][7]);
            }

            // chunk complete: score + running top-2 per row, zero acc
#pragma unroll
            for (int mi = 0; mi < 2; mi++)
#pragma unroll
            for (int blk = 0; blk < 4; blk++) {
                int i = mi * 4 + blk;
                int c = chunk * 128 + nw * 32 + blk * 8 + qc * 2;
                float en0 = __ldg(&g_eNorm[c]);
                float en1 = __ldg(&g_eNorm[c + 1]);
                int r0 = mi * 2, r1 = mi * 2 + 1;
                float v;
                v = __fsub_rn(__fadd_rn(zn[r0], en0), 2.0f * acc[i][0]);
                if (v < bv[r0]) { bw[r0] = bv[r0]; bj[r0] = bi[r0]; bv[r0] = v; bi[r0] = c; }
                else if (v < bw[r0]) { bw[r0] = v; bj[r0] = c; }
                v = __fsub_rn(__fadd_rn(zn[r0], en1), 2.0f * acc[i][1]);
                if (v < bv[r0]) { bw[r0] = bv[r0]; bj[r0] = bi[r0]; bv[r0] = v; bi[r0] = c + 1; }
                else if (v < bw[r0]) { bw[r0] = v; bj[r0] = c + 1; }
                v = __fsub_rn(__fadd_rn(zn[r1], en0), 2.0f * acc[i][2]);
                if (v < bv[r1]) { bw[r1] = bv[r1]; bj[r1] = bi[r1]; bv[r1] = v; bi[r1] = c; }
                else if (v < bw[r1]) { bw[r1] = v; bj[r1] = c; }
                v = __fsub_rn(__fadd_rn(zn[r1], en1), 2.0f * acc[i][3]);
                if (v < bv[r1]) { bw[r1] = bv[r1]; bj[r1] = bi[r1]; bv[r1] = v; bi[r1] = c + 1; }
                else if (v < bw[r1]) { bw[r1] = v; bj[r1] = c + 1; }
                acc[i][0] = acc[i][1] = acc[i][2] = acc[i][3] = 0.0f;
            }
        }
        __syncthreads();
    }

    // cross-thread merge: 32 (val,idx) pairs per row -> top-4
    float* redV = (float*)(smem + SM_B);                 // 64 rows x 32
    int*   redI = (int*)(smem + SM_B + 64 * 32 * 4);
    int slot = (nw * 4 + qc) * 2;
#pragma unroll
    for (int ri = 0; ri < 4; ri++) {
        int row = mw * 32 + gr + ri * 8;
        redV[row * 32 + slot] = bv[ri];     redI[row * 32 + slot] = bi[ri];
        redV[row * 32 + slot + 1] = bw[ri]; redI[row * 32 + slot + 1] = bj[ri];
    }
    __syncthreads();
    if (tid < M_CTA) {
        float v[32]; int ix[32];
#pragma unroll
        for (int t = 0; t < 32; t++) {
            v[t] = redV[tid * 32 + t];
            ix[t] = redI[tid * 32 + t];
        }
        float cv[4]; int ci[4];
#pragma unroll
        for (int s = 0; s < 4; s++) {
            float bvv = 3.4e38f; int bii = 0x7fffffff; int bp = 0;
#pragma unroll
            for (int t = 0; t < 32; t++) {
                if (v[t] < bvv || (v[t] == bvv && ix[t] < bii)) {
                    bvv = v[t]; bii = ix[t]; bp = t;
                }
            }
            cv[s] = bvv; ci[s] = bii;
            v[bp] = 3.4e38f; ix[bp] = 0x7fffffff;
        }
        g_cand[n0 + tid]  = make_int4(ci[0], ci[1], ci[2], ci[3]);
        g_candV[n0 + tid] = make_float4(cv[0], cv[1], cv[2], cv[3]);
    }
}

// ---------------------------------------------------------------------------
// Refine: one warp per vector. Wide approx top-2 gap -> HMMA winner provably
// the reference winner; else recompute <=4 candidate dots in fp64 and replay
// the exact fp32 score sequence with lowest-index tie-break.
__global__ void refineKernel(const float* __restrict__ cb) {
    int lane = threadIdx.x & 31, w = threadIdx.x >> 5;
    int n = blockIdx.x * 8 + w;
    int4   cd = g_cand[n];
    float4 cv = g_candV[n];
    if (cv.y - cv.x >= 1e-4f) {
        if (lane == 0) g_idx[n] = cd.x;
        return;
    }
    double zc[8];
    {
        uint4 u0 = ((const uint4*)(g_zs0 + (size_t)n * DIM))[lane];
        uint4 u1 = ((const uint4*)(g_zs1 + (size_t)n * DIM))[lane];
        uint4 u2 = ((const uint4*)(g_zs2 + (size_t)n * DIM))[lane];
        const uint32_t* w0 = &u0.x;
        const uint32_t* w1 = &u1.x;
        const uint32_t* w2 = &u2.x;
#pragma unroll
        for (int q = 0; q < 4; q++) {
            float2 f0 = __bfloat1622float2(*(const __nv_bfloat162*)&w0[q]);
            float2 f1 = __bfloat1622float2(*(const __nv_bfloat162*)&w1[q]);
            float2 f2 = __bfloat1622float2(*(const __nv_bfloat162*)&w2[q]);
            zc[q * 2]     = (double)f0.x + (double)f1.x + (double)f2.x;
            zc[q * 2 + 1] = (double)f0.y + (double)f1.y + (double)f2.y;
        }
    }
    float zn = (float)g_znD[n];
    float bs = 3.4e38f; int bi = 0x7fffffff;
    const int* kk = &cd.x;
#pragma unroll
    for (int j = 0; j < 4; j++) {
        int k = kk[j];
        const float4* crow = (const float4*)(cb + (size_t)k * DIM);
        float4 e0 = __ldg(&crow[lane * 2]);
        float4 e1 = __ldg(&crow[lane * 2 + 1]);
        double acc = zc[0] * (double)e0.x + zc[1] * (double)e0.y
                   + zc[2] * (double)e0.z + zc[3] * (double)e0.w
                   + zc[4] * (double)e1.x + zc[5] * (double)e1.y
                   + zc[6] * (double)e1.z + zc[7] * (double)e1.w;
#pragma unroll
        for (int o = 16; o > 0; o >>= 1)
            acc += __shfl_down_sync(0xffffffffu, acc, o);
        if (lane == 0) {
            float s = __fsub_rn(__fadd_rn(zn, __ldg(&g_eNorm[k])),
                                2.0f * (float)acc);
            if (s < bs || (s == bs && k < bi)) { bs = s; bi = k; }
        }
    }
    if (lane == 0) g_idx[n] = bi;
}

// ---------------------------------------------------------------------------
__global__ void zqLossKernel(const float* __restrict__ z,
                             const float* __restrict__ cb,
                             float* __restrict__ out) {
    int i4 = blockIdx.x * blockDim.x + threadIdx.x;
    float4 zv = ((const float4*)z)[i4];
    int base = i4 << 2;
    int hw = base & (HW - 1);
    int c  = (base >> 10) & (DIM - 1);
    int b  = base >> 18;
    int n  = b * HW + hw;
    float zz[4] = {zv.x, zv.y, zv.z, zv.w};
    float ls = 0.0f;
#pragma unroll
    for (int j = 0; j < 4; j++) {
        int k = g_idx[n + j];
        float q = __ldg(cb + k * DIM + c);
        float d = q - zz[j];
        out[ZQ_OFF + base + j] = zz[j] + d;
        ls += d * d;
    }
#pragma unroll
    for (int o = 16; o > 0; o >>= 1) ls += __shfl_down_sync(0xffffffffu, ls, o);
    __shared__ float ws[8];
    int lane = threadIdx.x & 31, w = threadIdx.x >> 5;
    if (lane == 0) ws[w] = ls;
    __syncthreads();
    if (threadIdx.x == 0) {
        float t = 0.0f;
#pragma unroll
        for (int i = 0; i < 8; i++) t += ws[i];
        atomicAdd(&g_lossSum, t);
    }
}

// Fused one-hot write (full rows, pure streaming) + indices + histogram
__global__ void onehotKernel(float* __restrict__ out) {
    int n = blockIdx.x;
    int k = g_idx[n];
    size_t base = ENC_OFF + (size_t)n * KC;
    int t = threadIdx.x;   // 256
#pragma unroll
    for (int q = 0; q < 2; q++) {
        int c2 = t + q * 256;
        float2 v = make_float2(0.0f, 0.0f);
        if (k == 2 * c2)     v.x = 1.0f;
        if (k == 2 * c2 + 1) v.y = 1.0f;
        *(float2*)(out + base + 2 * c2) = v;
    }
    if (t == 0) {
        out[IDX_OFF + n] = (float)k;
        atomicAdd(&g_counts[k], 1);
    }
}

__global__ void finalizeKernel(float* __restrict__ out) {
    int t = threadIdx.x;   // 1024
    float em = (float)g_counts[t] * (1.0f / (float)N_VEC);
    float v = em * logf(em + 1e-10f);
#pragma unroll
    for (int o = 16; o > 0; o >>= 1) v += __shfl_down_sync(0xffffffffu, v, o);
    __shared__ float ws[32];
    int lane = t & 31, w = t >> 5;
    if (lane == 0) ws[w] = v;
    __syncthreads();
    if (t == 0) {
        float s = 0.0f;
#pragma unroll
        for (int i = 0; i < 32; i++) s += ws[i];
        out[PERP_OFF] = expf(-s);
        float L = g_lossSum * (1.0f / 8388608.0f);
        out[0] = L + 0.25f * L;
    }
}

// ---------------------------------------------------------------------------
extern "C" void kernel_launch(void* const* d_in, const int* in_sizes, int n_in,
                              void* d_out, int out_size) {
    const float* z  = (const float*)d_in[0];
    const float* cb = (const float*)d_in[1];
    if (n_in >= 2 && in_sizes[0] == KC * DIM) {
        z  = (const float*)d_in[1];
        cb = (const float*)d_in[0];
    }
    float* out = (float*)d_out;

    cudaFuncSetAttribute(gemmArgmin,
                         cudaFuncAttributeMaxDynamicSharedMemorySize, GSMEM);

    initKernel<<<32, 1024>>>();
    splitCB<<<KC, 256>>>(cb);
    splitZ<<<dim3(32, 8, 32), 256>>>(z);
    gemmArgmin<<<N_VEC / M_CTA, 256, GSMEM>>>();
    refineKernel<<<N_VEC / 8, 256>>>(cb);
    zqLossKernel<<<8192, 256>>>(z, cb, out);
    onehotKernel<<<N_VEC, 256>>>(out);
    finalizeKernel<<<1, 1024>>>(out);
}

// round 8
// speedup vs baseline: 2.0671x; 1.0183x over previous
#include <cuda_runtime.h>
#include <cuda_bf16.h>
#include <cstdint>

// Problem constants
#define N_VEC   32768
#define DIM     256
#define KC      1024
#define HW      1024

// Output layout (flattened reference tuple, float32)
#define ZQ_OFF    1
#define PERP_OFF  8388609
#define ENC_OFF   8388610
#define IDX_OFF   41943042ull

// ---------------------------------------------------------------------------
// Device scratch (no allocations allowed)
__device__ __nv_bfloat16 g_zs0[N_VEC * DIM];   // z hi   (n-major [n][c])
__device__ __nv_bfloat16 g_zs1[N_VEC * DIM];   // z mid
__device__ __nv_bfloat16 g_zs2[N_VEC * DIM];   // z lo (refine only)
__device__ __nv_bfloat16 g_es0[KC * DIM];      // e hi   ([k][c])
__device__ __nv_bfloat16 g_es1[KC * DIM];      // e mid
__device__ double g_znD[N_VEC];                // ||z_n||^2 fp64
__device__ float  g_eNorm[KC];                 // fp32(||e_k||^2) fp64-acc
__device__ int4   g_cand[N_VEC];               // top-4 approx candidates
__device__ float4 g_candV[N_VEC];              // their approx scores
__device__ int    g_idx[N_VEC];
__device__ float  g_lossSum;
__device__ int    g_counts[KC];

// ---------------------------------------------------------------------------
__device__ __forceinline__ uint32_t smemU32(const void* p) {
    uint32_t a;
    asm("{ .reg .u64 t; cvta.to.shared.u64 t, %1; cvt.u32.u64 %0, t; }"
        : "=r"(a) : "l"(p));
    return a;
}
__device__ __forceinline__ void cpAsync16(uint32_t dst, const void* src) {
    asm volatile("cp.async.cg.shared.global [%0], [%1], 16;" :: "r"(dst), "l"(src));
}
#define CP_COMMIT() asm volatile("cp.async.commit_group;")
#define CP_WAIT1()  asm volatile("cp.async.wait_group 1;")
#define CP_WAIT0()  asm volatile("cp.async.wait_group 0;")

__device__ __forceinline__ void ldsm4(uint32_t& r0, uint32_t& r1,
                                      uint32_t& r2, uint32_t& r3, uint32_t a) {
    asm volatile("ldmatrix.sync.aligned.m8n8.x4.shared.b16 {%0,%1,%2,%3}, [%4];"
                 : "=r"(r0), "=r"(r1), "=r"(r2), "=r"(r3) : "r"(a));
}
__device__ __forceinline__ void mma16816(float* c, uint32_t a0, uint32_t a1,
                                         uint32_t a2, uint32_t a3,
                                         uint32_t b0, uint32_t b1) {
    asm volatile(
        "mma.sync.aligned.m16n8k16.row.col.f32.bf16.bf16.f32 "
        "{%0,%1,%2,%3}, {%4,%5,%6,%7}, {%8,%9}, {%0,%1,%2,%3};"
        : "+f"(c[0]), "+f"(c[1]), "+f"(c[2]), "+f"(c[3])
        : "r"(a0), "r"(a1), "r"(a2), "r"(a3), "r"(b0), "r"(b1));
}

// GEMM config: 512 threads, 16 warps = 4 M-warps x 4 N-warps, warp tile m16xn32
#define M_CTA   64
#define NTHR    512
#define SM_A    0            // 2 limbs x 64 rows x 512B = 65536
#define SM_B    65536        // 2 bufs x (128 codes x 512B) = 131072
#define GSMEM   196608

// ---------------------------------------------------------------------------
__global__ void initKernel() {
    int i = blockIdx.x * 1024 + threadIdx.x;   // grid 32 -> 32768
    g_znD[i] = 0.0;
    if (i < KC) g_counts[i] = 0;
    if (i == 0) g_lossSum = 0.0f;
}

// Split codebook into 2 exact bf16 limbs (GEMM) + fp64 norms. grid KC, 256.
__global__ void splitCB(const float* __restrict__ cb) {
    int k = blockIdx.x, c = threadIdx.x;
    float v = cb[k * DIM + c];
    __nv_bfloat16 h = __float2bfloat16_rn(v);
    float r1 = v - __bfloat162float(h);
    __nv_bfloat16 m = __float2bfloat16_rn(r1);
    size_t o = (size_t)k * DIM + c;
    g_es0[o] = h; g_es1[o] = m;

    double s = (double)v * (double)v;
#pragma unroll
    for (int off = 16; off > 0; off >>= 1) s += __shfl_down_sync(0xffffffffu, s, off);
    __shared__ double ws[8];
    int lane = c & 31, w = c >> 5;
    if (lane == 0) ws[w] = s;
    __syncthreads();
    if (c == 0) {
        double t = 0.0;
#pragma unroll
        for (int i = 0; i < 8; i++) t += ws[i];
        g_eNorm[k] = (float)t;
    }
}

// Split z (NCHW) into 3 exact bf16 limbs in n-major [n][c] + fp64 ||z_n||^2.
__global__ void splitZ(const float* __restrict__ z) {
    __shared__ float tile[32][33];
    __shared__ double colsum[32][8];
    int x = threadIdx.x & 31, y = threadIdx.x >> 5;
    int hw0 = blockIdx.x * 32, c0 = blockIdx.y * 32, b = blockIdx.z;
    const float* p = z + ((size_t)b * DIM + c0) * HW + hw0;
    double s = 0.0;
#pragma unroll
    for (int i = 0; i < 32; i += 8) {
        float v = p[(size_t)(y + i) * HW + x];
        tile[y + i][x] = v;
        s += (double)v * (double)v;
    }
    colsum[x][y] = s;
    __syncthreads();
    if (y == 0) {
        double t = 0.0;
#pragma unroll
        for (int j = 0; j < 8; j++) t += colsum[x][j];
        atomicAdd(&g_znD[b * HW + hw0 + x], t);
    }
#pragma unroll
    for (int i = 0; i < 32; i += 8) {
        float v = tile[x][y + i];               // c = c0+x, n = b*HW+hw0+y+i
        __nv_bfloat16 h = __float2bfloat16_rn(v);
        float r1 = v - __bfloat162float(h);
        __nv_bfloat16 m = __float2bfloat16_rn(r1);
        float r2 = r1 - __bfloat162float(m);
        __nv_bfloat16 l = __float2bfloat16_rn(r2);
        size_t o = (size_t)(b * HW + hw0 + y + i) * DIM + c0 + x;
        g_zs0[o] = h; g_zs1[o] = m; g_zs2[o] = l;
    }
}

// ---------------------------------------------------------------------------
__device__ __forceinline__ void loadB(uint32_t sb, int chunk, int el, int buf,
                                      int tid) {
    const __nv_bfloat16* src = (el == 0) ? g_es0 : g_es1;
    uint32_t bbase = sb + SM_B + buf * 65536;
#pragma unroll
    for (int it = 0; it < 8; it++) {
        int idx = tid + it * NTHR;
        int row = idx >> 5, u = idx & 31;
        const void* s = src + (size_t)(chunk * 128 + row) * DIM + u * 8;
        cpAsync16(bbase + row * 512 + ((u ^ (row & 7)) << 4), s);
    }
}

// Argmin GEMM via mma.sync m16n8k16 bf16. 3 limb products (zh*eh, zm*eh,
// zh*em), K_eff=768. 16 warps, warp tile m16 x n32, ldmatrix.x4 fragments,
// register double-buffered across ksteps. Emits TOP-4 candidates per vector.
__global__ __launch_bounds__(NTHR, 1) void gemmArgmin() {
    extern __shared__ char smem[];
    uint32_t sb = smemU32(smem);
    int tid = threadIdx.x;
    int n0 = blockIdx.x * M_CTA;
    int lane = tid & 31, wid = tid >> 5;
    int mw = wid & 3, nw = wid >> 2;       // 4 M-warps x 4 N-warps
    int gr = lane >> 2, qc = lane & 3;
    int hi = lane >> 4, swz = lane & 7;
    int l15 = lane & 15;

    {   // load A: z limbs 0,1; 64 rows x 512B each, swizzled
        const __nv_bfloat16* zsrc[2] = {g_zs0, g_zs1};
#pragma unroll
        for (int it = 0; it < 8; it++) {
            int idx = tid + it * NTHR;
            int limb = idx >> 11, rem = idx & 2047;
            int row = rem >> 5, u = rem & 31;
            const void* s = zsrc[limb] + (size_t)(n0 + row) * DIM + u * 8;
            cpAsync16(sb + SM_A + limb * 32768 + row * 512 +
                      ((u ^ (row & 7)) << 4), s);
        }
    }
    loadB(sb, 0, 0, 0, tid);
    CP_COMMIT();

    // rows handled by this thread: mw*16 + gr + {0,8}
    float zn[2];
    zn[0] = (float)g_znD[n0 + mw * 16 + gr];
    zn[1] = (float)g_znD[n0 + mw * 16 + gr + 8];
    float bv[2] = {3.4e38f, 3.4e38f}, bw[2] = {3.4e38f, 3.4e38f};
    int   bi[2] = {0, 0}, bj[2] = {0, 0};

    float acc[4][4];
#pragma unroll
    for (int i = 0; i < 4; i++)
#pragma unroll
        for (int j = 0; j < 4; j++) acc[i][j] = 0.0f;

    uint32_t aa0 = sb + SM_A + (mw * 16 + l15) * 512;     // z limb 0
    uint32_t aa1 = aa0 + 32768;                            // z limb 1
    uint32_t bRow = (nw * 32 + l15) * 512;

    for (int s = 0; s < 16; s++) {
        int chunk = s >> 1, el = s & 1, buf = s & 1;
        if (s + 1 < 16) {
            loadB(sb, (s + 1) >> 1, (s + 1) & 1, buf ^ 1, tid);
            CP_COMMIT();
            CP_WAIT1();
        } else {
            CP_WAIT0();
        }
        __syncthreads();

        uint32_t bb = sb + SM_B + buf * 65536 + bRow;
        uint32_t off0 = (uint32_t)((hi ^ swz) << 4);

        if (el == 0) {
            // eh stage: products zh*eh and zm*eh (8 MMAs / 4 LDSM per kstep)
            uint32_t A0[2][4], A1[2][4], Bf[2][8];
            ldsm4(Bf[0][0], Bf[0][1], Bf[0][2], Bf[0][3], bb + off0);
            ldsm4(Bf[0][4], Bf[0][5], Bf[0][6], Bf[0][7], bb + 8192 + off0);
            ldsm4(A0[0][0], A0[0][1], A0[0][2], A0[0][3], aa0 + off0);
            ldsm4(A1[0][0], A1[0][1], A1[0][2], A1[0][3], aa1 + off0);
#pragma unroll
            for (int ks = 0; ks < 16; ks++) {
                int cur = ks & 1, nxt = cur ^ 1;
                if (ks < 15) {
                    uint32_t off = (uint32_t)(((2 * (ks + 1) + hi) ^ swz) << 4);
                    ldsm4(Bf[nxt][0], Bf[nxt][1], Bf[nxt][2], Bf[nxt][3], bb + off);
                    ldsm4(Bf[nxt][4], Bf[nxt][5], Bf[nxt][6], Bf[nxt][7], bb + 8192 + off);
                    ldsm4(A0[nxt][0], A0[nxt][1], A0[nxt][2], A0[nxt][3], aa0 + off);
                    ldsm4(A1[nxt][0], A1[nxt][1], A1[nxt][2], A1[nxt][3], aa1 + off);
                }
                mma16816(acc[0], A0[cur][0], A0[cur][1], A0[cur][2], A0[cur][3], Bf[cur][0], Bf[cur][2]);
                mma16816(acc[1], A0[cur][0], A0[cur][1], A0[cur][2], A0[cur][3], Bf[cur][1], Bf[cur][3]);
                mma16816(acc[2], A0[cur][0], A0[cur][1], A0[cur][2], A0[cur][3], Bf[cur][4], Bf[cur][6]);
                mma16816(acc[3], A0[cur][0], A0[cur][1], A0[cur][2], A0[cur][3], Bf[cur][5], Bf[cur][7]);
                mma16816(acc[0], A1[cur][0], A1[cur][1], A1[cur][2], A1[cur][3], Bf[cur][0], Bf[cur][2]);
                mma16816(acc[1], A1[cur][0], A1[cur][1], A1[cur][2], A1[cur][3], Bf[cur][1], Bf[cur][3]);
                mma16816(acc[2], A1[cur][0], A1[cur][1], A1[cur][2], A1[cur][3], Bf[cur][4], Bf[cur][6]);
                mma16816(acc[3], A1[cur][0], A1[cur][1], A1[cur][2], A1[cur][3], Bf[cur][5], Bf[cur][7]);
            }
        } else {
            // em stage: product zh*em (4 MMAs / 3 LDSM per kstep)
            uint32_t A0[2][4], Bf[2][8];
            ldsm4(Bf[0][0], Bf[0][1], Bf[0][2], Bf[0][3], bb + off0);
            ldsm4(Bf[0][4], Bf[0][5], Bf[0][6], Bf[0][7], bb + 8192 + off0);
            ldsm4(A0[0][0], A0[0][1], A0[0][2], A0[0][3], aa0 + off0);
#pragma unroll
            for (int ks = 0; ks < 16; ks++) {
                int cur = ks & 1, nxt = cur ^ 1;
                if (ks < 15) {
                    uint32_t off = (uint32_t)(((2 * (ks + 1) + hi) ^ swz) << 4);
                    ldsm4(Bf[nxt][0], Bf[nxt][1], Bf[nxt][2], Bf[nxt][3], bb + off);
                    ldsm4(Bf[nxt][4], Bf[nxt][5], Bf[nxt][6], Bf[nxt][7], bb + 8192 + off);
                    ldsm4(A0[nxt][0], A0[nxt][1], A0[nxt][2], A0[nxt][3], aa0 + off);
                }
                mma16816(acc[0], A0[cur][0], A0[cur][1], A0[cur][2], A0[cur][3], Bf[cur][0], Bf[cur][2]);
                mma16816(acc[1], A0[cur][0], A0[cur][1], A0[cur][2], A0[cur][3], Bf[cur][1], Bf[cur][3]);
                mma16816(acc[2], A0[cur][0], A0[cur][1], A0[cur][2], A0[cur][3], Bf[cur][4], Bf[cur][6]);
                mma16816(acc[3], A0[cur][0], A0[cur][1], A0[cur][2], A0[cur][3], Bf[cur][5], Bf[cur][7]);
            }

            // chunk complete: score + running top-2 per row, zero acc
#pragma unroll
            for (int blk = 0; blk < 4; blk++) {
                int c = chunk * 128 + nw * 32 + blk * 8 + qc * 2;
                float en0 = __ldg(&g_eNorm[c]);
                float en1 = __ldg(&g_eNorm[c + 1]);
                float v;
                v = __fsub_rn(__fadd_rn(zn[0], en0), 2.0f * acc[blk][0]);
                if (v < bv[0]) { bw[0] = bv[0]; bj[0] = bi[0]; bv[0] = v; bi[0] = c; }
                else if (v < bw[0]) { bw[0] = v; bj[0] = c; }
                v = __fsub_rn(__fadd_rn(zn[0], en1), 2.0f * acc[blk][1]);
                if (v < bv[0]) { bw[0] = bv[0]; bj[0] = bi[0]; bv[0] = v; bi[0] = c + 1; }
                else if (v < bw[0]) { bw[0] = v; bj[0] = c + 1; }
                v = __fsub_rn(__fadd_rn(zn[1], en0), 2.0f * acc[blk][2]);
                if (v < bv[1]) { bw[1] = bv[1]; bj[1] = bi[1]; bv[1] = v; bi[1] = c; }
                else if (v < bw[1]) { bw[1] = v; bj[1] = c; }
                v = __fsub_rn(__fadd_rn(zn[1], en1), 2.0f * acc[blk][3]);
                if (v < bv[1]) { bw[1] = bv[1]; bj[1] = bi[1]; bv[1] = v; bi[1] = c + 1; }
                else if (v < bw[1]) { bw[1] = v; bj[1] = c + 1; }
                acc[blk][0] = acc[blk][1] = acc[blk][2] = acc[blk][3] = 0.0f;
            }
        }
        __syncthreads();
    }

    // cross-thread merge: 32 (val,idx) pairs per row -> top-4
    float* redV = (float*)(smem + SM_B);                 // 64 rows x 32
    int*   redI = (int*)(smem + SM_B + 64 * 32 * 4);
    int slot = (nw * 4 + qc) * 2;
#pragma unroll
    for (int ri = 0; ri < 2; ri++) {
        int row = mw * 16 + gr + ri * 8;
        redV[row * 32 + slot] = bv[ri];     redI[row * 32 + slot] = bi[ri];
        redV[row * 32 + slot + 1] = bw[ri]; redI[row * 32 + slot + 1] = bj[ri];
    }
    __syncthreads();
    if (tid < M_CTA) {
        float v[32]; int ix[32];
#pragma unroll
        for (int t = 0; t < 32; t++) {
            v[t] = redV[tid * 32 + t];
            ix[t] = redI[tid * 32 + t];
        }
        float cv[4]; int ci[4];
#pragma unroll
        for (int s = 0; s < 4; s++) {
            float bvv = 3.4e38f; int bii = 0x7fffffff; int bp = 0;
#pragma unroll
            for (int t = 0; t < 32; t++) {
                if (v[t] < bvv || (v[t] == bvv && ix[t] < bii)) {
                    bvv = v[t]; bii = ix[t]; bp = t;
                }
            }
            cv[s] = bvv; ci[s] = bii;
            v[bp] = 3.4e38f; ix[bp] = 0x7fffffff;
        }
        g_cand[n0 + tid]  = make_int4(ci[0], ci[1], ci[2], ci[3]);
        g_candV[n0 + tid] = make_float4(cv[0], cv[1], cv[2], cv[3]);
    }
}

// ---------------------------------------------------------------------------
// Refine: one warp per vector. Wide approx top-2 gap -> HMMA winner provably
// the reference winner; else recompute <=4 candidate dots in fp64 and replay
// the exact fp32 score sequence with lowest-index tie-break.
__global__ void refineKernel(const float* __restrict__ cb) {
    int lane = threadIdx.x & 31, w = threadIdx.x >> 5;
    int n = blockIdx.x * 8 + w;
    int4   cd = g_cand[n];
    float4 cv = g_candV[n];
    if (cv.y - cv.x >= 1e-4f) {
        if (lane == 0) g_idx[n] = cd.x;
        return;
    }
    double zc[8];
    {
        uint4 u0 = ((const uint4*)(g_zs0 + (size_t)n * DIM))[lane];
        uint4 u1 = ((const uint4*)(g_zs1 + (size_t)n * DIM))[lane];
        uint4 u2 = ((const uint4*)(g_zs2 + (size_t)n * DIM))[lane];
        const uint32_t* w0 = &u0.x;
        const uint32_t* w1 = &u1.x;
        const uint32_t* w2 = &u2.x;
#pragma unroll
        for (int q = 0; q < 4; q++) {
            float2 f0 = __bfloat1622float2(*(const __nv_bfloat162*)&w0[q]);
            float2 f1 = __bfloat1622float2(*(const __nv_bfloat162*)&w1[q]);
            float2 f2 = __bfloat1622float2(*(const __nv_bfloat162*)&w2[q]);
            zc[q * 2]     = (double)f0.x + (double)f1.x + (double)f2.x;
            zc[q * 2 + 1] = (double)f0.y + (double)f1.y + (double)f2.y;
        }
    }
    float zn = (float)g_znD[n];
    float bs = 3.4e38f; int bi = 0x7fffffff;
    const int* kk = &cd.x;
#pragma unroll
    for (int j = 0; j < 4; j++) {
        int k = kk[j];
        const float4* crow = (const float4*)(cb + (size_t)k * DIM);
        float4 e0 = __ldg(&crow[lane * 2]);
        float4 e1 = __ldg(&crow[lane * 2 + 1]);
        double acc = zc[0] * (double)e0.x + zc[1] * (double)e0.y
                   + zc[2] * (double)e0.z + zc[3] * (double)e0.w
                   + zc[4] * (double)e1.x + zc[5] * (double)e1.y
                   + zc[6] * (double)e1.z + zc[7] * (double)e1.w;
#pragma unroll
        for (int o = 16; o > 0; o >>= 1)
            acc += __shfl_down_sync(0xffffffffu, acc, o);
        if (lane == 0) {
            float s = __fsub_rn(__fadd_rn(zn, __ldg(&g_eNorm[k])),
                                2.0f * (float)acc);
            if (s < bs || (s == bs && k < bi)) { bs = s; bi = k; }
        }
    }
    if (lane == 0) g_idx[n] = bi;
}

// ---------------------------------------------------------------------------
__global__ void zqLossKernel(const float* __restrict__ z,
                             const float* __restrict__ cb,
                             float* __restrict__ out) {
    int i4 = blockIdx.x * blockDim.x + threadIdx.x;
    float4 zv = ((const float4*)z)[i4];
    int base = i4 << 2;
    int hw = base & (HW - 1);
    int c  = (base >> 10) & (DIM - 1);
    int b  = base >> 18;
    int n  = b * HW + hw;
    float zz[4] = {zv.x, zv.y, zv.z, zv.w};
    float ls = 0.0f;
#pragma unroll
    for (int j = 0; j < 4; j++) {
        int k = g_idx[n + j];
        float q = __ldg(cb + k * DIM + c);
        float d = q - zz[j];
        out[ZQ_OFF + base + j] = zz[j] + d;
        ls += d * d;
    }
#pragma unroll
    for (int o = 16; o > 0; o >>= 1) ls += __shfl_down_sync(0xffffffffu, ls, o);
    __shared__ float ws[8];
    int lane = threadIdx.x & 31, w = threadIdx.x >> 5;
    if (lane == 0) ws[w] = ls;
    __syncthreads();
    if (threadIdx.x == 0) {
        float t = 0.0f;
#pragma unroll
        for (int i = 0; i < 8; i++) t += ws[i];
        atomicAdd(&g_lossSum, t);
    }
}

// Fused one-hot write (full rows, pure streaming) + indices + histogram
__global__ void onehotKernel(float* __restrict__ out) {
    int n = blockIdx.x;
    int k = g_idx[n];
    size_t base = ENC_OFF + (size_t)n * KC;
    int t = threadIdx.x;   // 256
#pragma unroll
    for (int q = 0; q < 2; q++) {
        int c2 = t + q * 256;
        float2 v = make_float2(0.0f, 0.0f);
        if (k == 2 * c2)     v.x = 1.0f;
        if (k == 2 * c2 + 1) v.y = 1.0f;
        *(float2*)(out + base + 2 * c2) = v;
    }
    if (t == 0) {
        out[IDX_OFF + n] = (float)k;
        atomicAdd(&g_counts[k], 1);
    }
}

__global__ void finalizeKernel(float* __restrict__ out) {
    int t = threadIdx.x;   // 1024
    float em = (float)g_counts[t] * (1.0f / (float)N_VEC);
    float v = em * logf(em + 1e-10f);
#pragma unroll
    for (int o = 16; o > 0; o >>= 1) v += __shfl_down_sync(0xffffffffu, v, o);
    __shared__ float ws[32];
    int lane = t & 31, w = t >> 5;
    if (lane == 0) ws[w] = v;
    __syncthreads();
    if (t == 0) {
        float s = 0.0f;
#pragma unroll
        for (int i = 0; i < 32; i++) s += ws[i];
        out[PERP_OFF] = expf(-s);
        float L = g_lossSum * (1.0f / 8388608.0f);
        out[0] = L + 0.25f * L;
    }
}

// ---------------------------------------------------------------------------
extern "C" void kernel_launch(void* const* d_in, const int* in_sizes, int n_in,
                              void* d_out, int out_size) {
    const float* z  = (const float*)d_in[0];
    const float* cb = (const float*)d_in[1];
    if (n_in >= 2 && in_sizes[0] == KC * DIM) {
        z  = (const float*)d_in[1];
        cb = (const float*)d_in[0];
    }
    float* out = (float*)d_out;

    cudaFuncSetAttribute(gemmArgmin,
                         cudaFuncAttributeMaxDynamicSharedMemorySize, GSMEM);

    initKernel<<<32, 1024>>>();
    splitCB<<<KC, 256>>>(cb);
    splitZ<<<dim3(32, 8, 32), 256>>>(z);
    gemmArgmin<<<N_VEC / M_CTA, NTHR, GSMEM>>>();
    refineKernel<<<N_VEC / 8, 256>>>(cb);
    zqLossKernel<<<8192, 256>>>(z, cb, out);
    onehotKernel<<<N_VEC, 256>>>(out);
    finalizeKernel<<<1, 1024>>>(out);
}

// round 9
// speedup vs baseline: 3.0814x; 1.4907x over previous
#include <cuda_runtime.h>
#include <cuda_fp16.h>
#include <cstdint>

// Problem constants
#define N_VEC   32768
#define DIM     256
#define KC      1024
#define HW      1024

// Output layout (flattened reference tuple, float32)
#define ZQ_OFF    1
#define PERP_OFF  8388609
#define ENC_OFF   8388610
#define IDX_OFF   41943042ull

// ---------------------------------------------------------------------------
// Device scratch (no allocations allowed)
__device__ __half  g_zh[N_VEC * DIM];          // fp16(z), n-major [n][c]
__device__ __half  g_eh[KC * DIM];             // fp16(e), [k][c]
__device__ double  g_znD[N_VEC];               // ||z_n||^2 fp64
__device__ float   g_eNorm[KC];                // fp32(||e_k||^2) fp64-acc
__device__ int4    g_cand[N_VEC];              // top-4 approx candidates
__device__ float4  g_candV[N_VEC];             // their approx scores
__device__ int     g_idx[N_VEC];
__device__ float   g_lossSum;
__device__ int     g_counts[KC];

// ---------------------------------------------------------------------------
__device__ __forceinline__ uint32_t smemU32(const void* p) {
    uint32_t a;
    asm("{ .reg .u64 t; cvta.to.shared.u64 t, %1; cvt.u32.u64 %0, t; }"
        : "=r"(a) : "l"(p));
    return a;
}
__device__ __forceinline__ void cpAsync16(uint32_t dst, const void* src) {
    asm volatile("cp.async.cg.shared.global [%0], [%1], 16;" :: "r"(dst), "l"(src));
}
#define CP_COMMIT() asm volatile("cp.async.commit_group;")
#define CP_WAIT1()  asm volatile("cp.async.wait_group 1;")
#define CP_WAIT0()  asm volatile("cp.async.wait_group 0;")

__device__ __forceinline__ void ldsm4(uint32_t& r0, uint32_t& r1,
                                      uint32_t& r2, uint32_t& r3, uint32_t a) {
    asm volatile("ldmatrix.sync.aligned.m8n8.x4.shared.b16 {%0,%1,%2,%3}, [%4];"
                 : "=r"(r0), "=r"(r1), "=r"(r2), "=r"(r3) : "r"(a));
}
__device__ __forceinline__ void mma16816h(float* c, uint32_t a0, uint32_t a1,
                                          uint32_t a2, uint32_t a3,
                                          uint32_t b0, uint32_t b1) {
    asm volatile(
        "mma.sync.aligned.m16n8k16.row.col.f32.f16.f16.f32 "
        "{%0,%1,%2,%3}, {%4,%5,%6,%7}, {%8,%9}, {%0,%1,%2,%3};"
        : "+f"(c[0]), "+f"(c[1]), "+f"(c[2]), "+f"(c[3])
        : "r"(a0), "r"(a1), "r"(a2), "r"(a3), "r"(b0), "r"(b1));
}

// GEMM config: 512 threads = 4 M-warps x 4 N-warps, warp tile m16 x n32
#define M_CTA   64
#define NTHR    512
#define SM_A    0            // 64 rows x 512B = 32768
#define SM_B    32768        // 2 bufs x (128 codes x 512B) = 131072
#define GSMEM   163840

// ---------------------------------------------------------------------------
__global__ void initKernel() {
    int i = blockIdx.x * 1024 + threadIdx.x;   // grid 32 -> 32768
    g_znD[i] = 0.0;
    if (i < KC) g_counts[i] = 0;
    if (i == 0) g_lossSum = 0.0f;
}

// fp16 codebook + fp64 norms. grid KC, block 256.
__global__ void splitCB(const float* __restrict__ cb) {
    int k = blockIdx.x, c = threadIdx.x;
    float v = cb[k * DIM + c];
    g_eh[(size_t)k * DIM + c] = __float2half_rn(v);

    double s = (double)v * (double)v;
#pragma unroll
    for (int off = 16; off > 0; off >>= 1) s += __shfl_down_sync(0xffffffffu, s, off);
    __shared__ double ws[8];
    int lane = c & 31, w = c >> 5;
    if (lane == 0) ws[w] = s;
    __syncthreads();
    if (c == 0) {
        double t = 0.0;
#pragma unroll
        for (int i = 0; i < 8; i++) t += ws[i];
        g_eNorm[k] = (float)t;
    }
}

// fp16(z) in n-major [n][c] + fp64 ||z_n||^2. Transpose via smem.
__global__ void splitZ(const float* __restrict__ z) {
    __shared__ float tile[32][33];
    __shared__ double colsum[32][8];
    int x = threadIdx.x & 31, y = threadIdx.x >> 5;
    int hw0 = blockIdx.x * 32, c0 = blockIdx.y * 32, b = blockIdx.z;
    const float* p = z + ((size_t)b * DIM + c0) * HW + hw0;
    double s = 0.0;
#pragma unroll
    for (int i = 0; i < 32; i += 8) {
        float v = p[(size_t)(y + i) * HW + x];
        tile[y + i][x] = v;
        s += (double)v * (double)v;
    }
    colsum[x][y] = s;
    __syncthreads();
    if (y == 0) {
        double t = 0.0;
#pragma unroll
        for (int j = 0; j < 8; j++) t += colsum[x][j];
        atomicAdd(&g_znD[b * HW + hw0 + x], t);
    }
#pragma unroll
    for (int i = 0; i < 32; i += 8) {
        float v = tile[x][y + i];               // c = c0+x, n = b*HW+hw0+y+i
        g_zh[(size_t)(b * HW + hw0 + y + i) * DIM + c0 + x] = __float2half_rn(v);
    }
}

// ---------------------------------------------------------------------------
__device__ __forceinline__ void loadB(uint32_t sb, int chunk, int buf, int tid) {
    uint32_t bbase = sb + SM_B + buf * 65536;
#pragma unroll
    for (int it = 0; it < 8; it++) {
        int idx = tid + it * NTHR;
        int row = idx >> 5, u = idx & 31;
        const void* s = g_eh + (size_t)(chunk * 128 + row) * DIM + u * 8;
        cpAsync16(bbase + row * 512 + ((u ^ (row & 7)) << 4), s);
    }
}

// Candidate GEMM via mma.sync m16n8k16 fp16: single product zh*eh, K=256.
// Score error sigma ~5e-6 << 2e-4 refine threshold. 16 warps, warp tile
// m16 x n32, register double-buffered fragments. Emits TOP-4 per vector.
__global__ __launch_bounds__(NTHR, 1) void gemmArgmin() {
    extern __shared__ char smem[];
    uint32_t sb = smemU32(smem);
    int tid = threadIdx.x;
    int n0 = blockIdx.x * M_CTA;
    int lane = tid & 31, wid = tid >> 5;
    int mw = wid & 3, nw = wid >> 2;       // 4 M-warps x 4 N-warps
    int gr = lane >> 2, qc = lane & 3;
    int hi = lane >> 4, swz = lane & 7;
    int l15 = lane & 15;

    {   // load A: 64 rows x 512B, swizzled
#pragma unroll
        for (int it = 0; it < 4; it++) {
            int idx = tid + it * NTHR;
            int row = idx >> 5, u = idx & 31;
            const void* s = g_zh + (size_t)(n0 + row) * DIM + u * 8;
            cpAsync16(sb + SM_A + row * 512 + ((u ^ (row & 7)) << 4), s);
        }
    }
    loadB(sb, 0, 0, tid);
    CP_COMMIT();

    // rows handled by this thread: mw*16 + gr + {0,8}
    float zn[2];
    zn[0] = (float)g_znD[n0 + mw * 16 + gr];
    zn[1] = (float)g_znD[n0 + mw * 16 + gr + 8];
    float bv[2] = {3.4e38f, 3.4e38f}, bw[2] = {3.4e38f, 3.4e38f};
    int   bi[2] = {0, 0}, bj[2] = {0, 0};

    float acc[4][4];
#pragma unroll
    for (int i = 0; i < 4; i++)
#pragma unroll
        for (int j = 0; j < 4; j++) acc[i][j] = 0.0f;

    uint32_t aa = sb + SM_A + (mw * 16 + l15) * 512;
    uint32_t bRow = (nw * 32 + l15) * 512;

    for (int s = 0; s < 8; s++) {
        int buf = s & 1;
        if (s + 1 < 8) {
            loadB(sb, s + 1, buf ^ 1, tid);
            CP_COMMIT();
            CP_WAIT1();
        } else {
            CP_WAIT0();
        }
        __syncthreads();

        uint32_t bb = sb + SM_B + buf * 65536 + bRow;
        uint32_t off0 = (uint32_t)((hi ^ swz) << 4);

        uint32_t A[2][4], Bf[2][8];
        ldsm4(Bf[0][0], Bf[0][1], Bf[0][2], Bf[0][3], bb + off0);
        ldsm4(Bf[0][4], Bf[0][5], Bf[0][6], Bf[0][7], bb + 8192 + off0);
        ldsm4(A[0][0], A[0][1], A[0][2], A[0][3], aa + off0);
#pragma unroll
        for (int ks = 0; ks < 16; ks++) {
            int cur = ks & 1, nxt = cur ^ 1;
            if (ks < 15) {
                uint32_t off = (uint32_t)(((2 * (ks + 1) + hi) ^ swz) << 4);
                ldsm4(Bf[nxt][0], Bf[nxt][1], Bf[nxt][2], Bf[nxt][3], bb + off);
                ldsm4(Bf[nxt][4], Bf[nxt][5], Bf[nxt][6], Bf[nxt][7], bb + 8192 + off);
                ldsm4(A[nxt][0], A[nxt][1], A[nxt][2], A[nxt][3], aa + off);
            }
            mma16816h(acc[0], A[cur][0], A[cur][1], A[cur][2], A[cur][3], Bf[cur][0], Bf[cur][2]);
            mma16816h(acc[1], A[cur][0], A[cur][1], A[cur][2], A[cur][3], Bf[cur][1], Bf[cur][3]);
            mma16816h(acc[2], A[cur][0], A[cur][1], A[cur][2], A[cur][3], Bf[cur][4], Bf[cur][6]);
            mma16816h(acc[3], A[cur][0], A[cur][1], A[cur][2], A[cur][3], Bf[cur][5], Bf[cur][7]);
        }

        // chunk complete: score + running top-2 per row, zero acc
#pragma unroll
        for (int blk = 0; blk < 4; blk++) {
            int c = s * 128 + nw * 32 + blk * 8 + qc * 2;
            float en0 = __ldg(&g_eNorm[c]);
            float en1 = __ldg(&g_eNorm[c + 1]);
            float v;
            v = __fsub_rn(__fadd_rn(zn[0], en0), 2.0f * acc[blk][0]);
            if (v < bv[0]) { bw[0] = bv[0]; bj[0] = bi[0]; bv[0] = v; bi[0] = c; }
            else if (v < bw[0]) { bw[0] = v; bj[0] = c; }
            v = __fsub_rn(__fadd_rn(zn[0], en1), 2.0f * acc[blk][1]);
            if (v < bv[0]) { bw[0] = bv[0]; bj[0] = bi[0]; bv[0] = v; bi[0] = c + 1; }
            else if (v < bw[0]) { bw[0] = v; bj[0] = c + 1; }
            v = __fsub_rn(__fadd_rn(zn[1], en0), 2.0f * acc[blk][2]);
            if (v < bv[1]) { bw[1] = bv[1]; bj[1] = bi[1]; bv[1] = v; bi[1] = c; }
            else if (v < bw[1]) { bw[1] = v; bj[1] = c; }
            v = __fsub_rn(__fadd_rn(zn[1], en1), 2.0f * acc[blk][3]);
            if (v < bv[1]) { bw[1] = bv[1]; bj[1] = bi[1]; bv[1] = v; bi[1] = c + 1; }
            else if (v < bw[1]) { bw[1] = v; bj[1] = c + 1; }
            acc[blk][0] = acc[blk][1] = acc[blk][2] = acc[blk][3] = 0.0f;
        }
        __syncthreads();
    }

    // cross-thread merge: 32 (val,idx) pairs per row -> top-4
    float* redV = (float*)(smem + SM_B);                 // 64 rows x 32
    int*   redI = (int*)(smem + SM_B + 64 * 32 * 4);
    int slot = (nw * 4 + qc) * 2;
#pragma unroll
    for (int ri = 0; ri < 2; ri++) {
        int row = mw * 16 + gr + ri * 8;
        redV[row * 32 + slot] = bv[ri];     redI[row * 32 + slot] = bi[ri];
        redV[row * 32 + slot + 1] = bw[ri]; redI[row * 32 + slot + 1] = bj[ri];
    }
    __syncthreads();
    if (tid < M_CTA) {
        float v[32]; int ix[32];
#pragma unroll
        for (int t = 0; t < 32; t++) {
            v[t] = redV[tid * 32 + t];
            ix[t] = redI[tid * 32 + t];
        }
        float cv[4]; int ci[4];
#pragma unroll
        for (int s = 0; s < 4; s++) {
            float bvv = 3.4e38f; int bii = 0x7fffffff; int bp = 0;
#pragma unroll
            for (int t = 0; t < 32; t++) {
                if (v[t] < bvv || (v[t] == bvv && ix[t] < bii)) {
                    bvv = v[t]; bii = ix[t]; bp = t;
                }
            }
            cv[s] = bvv; ci[s] = bii;
            v[bp] = 3.4e38f; ix[bp] = 0x7fffffff;
        }
        g_cand[n0 + tid]  = make_int4(ci[0], ci[1], ci[2], ci[3]);
        g_candV[n0 + tid] = make_float4(cv[0], cv[1], cv[2], cv[3]);
    }
}

// ---------------------------------------------------------------------------
// Refine: one warp per vector. Wide approx top-2 gap -> fp16 winner provably
// the reference winner (gap >= 2e-4 >> 4-sigma error + 6 fp32 cells); else
// recompute <=4 candidate dots in fp64 from the ORIGINAL z and replay the
// exact fp32 score sequence with lowest-index tie-break.
__global__ void refineKernel(const float* __restrict__ z,
                             const float* __restrict__ cb) {
    int lane = threadIdx.x & 31, w = threadIdx.x >> 5;
    int n = blockIdx.x * 8 + w;
    int4   cd = g_cand[n];
    float4 cv = g_candV[n];
    if (cv.y - cv.x >= 2e-4f) {
        if (lane == 0) g_idx[n] = cd.x;
        return;
    }
    // exact z from original NCHW tensor: z[b][c][hw], strided reads
    int b = n >> 10, hw = n & (HW - 1);
    const float* zp = z + (size_t)b * DIM * HW + hw;
    double zc[8];
#pragma unroll
    for (int q = 0; q < 8; q++)
        zc[q] = (double)__ldg(zp + (size_t)(lane * 8 + q) * HW);

    float zn = (float)g_znD[n];
    float bs = 3.4e38f; int bi = 0x7fffffff;
    const int* kk = &cd.x;
#pragma unroll
    for (int j = 0; j < 4; j++) {
        int k = kk[j];
        const float4* crow = (const float4*)(cb + (size_t)k * DIM);
        float4 e0 = __ldg(&crow[lane * 2]);
        float4 e1 = __ldg(&crow[lane * 2 + 1]);
        double acc = zc[0] * (double)e0.x + zc[1] * (double)e0.y
                   + zc[2] * (double)e0.z + zc[3] * (double)e0.w
                   + zc[4] * (double)e1.x + zc[5] * (double)e1.y
                   + zc[6] * (double)e1.z + zc[7] * (double)e1.w;
#pragma unroll
        for (int o = 16; o > 0; o >>= 1)
            acc += __shfl_down_sync(0xffffffffu, acc, o);
        if (lane == 0) {
            float s = __fsub_rn(__fadd_rn(zn, __ldg(&g_eNorm[k])),
                                2.0f * (float)acc);
            if (s < bs || (s == bs && k < bi)) { bs = s; bi = k; }
        }
    }
    if (lane == 0) g_idx[n] = bi;
}

// ---------------------------------------------------------------------------
__global__ void zqLossKernel(const float* __restrict__ z,
                             const float* __restrict__ cb,
                             float* __restrict__ out) {
    int i4 = blockIdx.x * blockDim.x + threadIdx.x;
    float4 zv = ((const float4*)z)[i4];
    int base = i4 << 2;
    int hw = base & (HW - 1);
    int c  = (base >> 10) & (DIM - 1);
    int b  = base >> 18;
    int n  = b * HW + hw;
    float zz[4] = {zv.x, zv.y, zv.z, zv.w};
    float ls = 0.0f;
#pragma unroll
    for (int j = 0; j < 4; j++) {
        int k = g_idx[n + j];
        float q = __ldg(cb + k * DIM + c);
        float d = q - zz[j];
        out[ZQ_OFF + base + j] = zz[j] + d;
        ls += d * d;
    }
#pragma unroll
    for (int o = 16; o > 0; o >>= 1) ls += __shfl_down_sync(0xffffffffu, ls, o);
    __shared__ float ws[8];
    int lane = threadIdx.x & 31, w = threadIdx.x >> 5;
    if (lane == 0) ws[w] = ls;
    __syncthreads();
    if (threadIdx.x == 0) {
        float t = 0.0f;
#pragma unroll
        for (int i = 0; i < 8; i++) t += ws[i];
        atomicAdd(&g_lossSum, t);
    }
}

// Fused one-hot write (full rows, pure streaming) + indices + histogram
__global__ void onehotKernel(float* __restrict__ out) {
    int n = blockIdx.x;
    int k = g_idx[n];
    size_t base = ENC_OFF + (size_t)n * KC;
    int t = threadIdx.x;   // 256
#pragma unroll
    for (int q = 0; q < 2; q++) {
        int c2 = t + q * 256;
        float2 v = make_float2(0.0f, 0.0f);
        if (k == 2 * c2)     v.x = 1.0f;
        if (k == 2 * c2 + 1) v.y = 1.0f;
        *(float2*)(out + base + 2 * c2) = v;
    }
    if (t == 0) {
        out[IDX_OFF + n] = (float)k;
        atomicAdd(&g_counts[k], 1);
    }
}

__global__ void finalizeKernel(float* __restrict__ out) {
    int t = threadIdx.x;   // 1024
    float em = (float)g_counts[t] * (1.0f / (float)N_VEC);
    float v = em * logf(em + 1e-10f);
#pragma unroll
    for (int o = 16; o > 0; o >>= 1) v += __shfl_down_sync(0xffffffffu, v, o);
    __shared__ float ws[32];
    int lane = t & 31, w = t >> 5;
    if (lane == 0) ws[w] = v;
    __syncthreads();
    if (t == 0) {
        float s = 0.0f;
#pragma unroll
        for (int i = 0; i < 32; i++) s += ws[i];
        out[PERP_OFF] = expf(-s);
        float L = g_lossSum * (1.0f / 8388608.0f);
        out[0] = L + 0.25f * L;
    }
}

// ---------------------------------------------------------------------------
extern "C" void kernel_launch(void* const* d_in, const int* in_sizes, int n_in,
                              void* d_out, int out_size) {
    const float* z  = (const float*)d_in[0];
    const float* cb = (const float*)d_in[1];
    if (n_in >= 2 && in_sizes[0] == KC * DIM) {
        z  = (const float*)d_in[1];
        cb = (const float*)d_in[0];
    }
    float* out = (float*)d_out;

    cudaFuncSetAttribute(gemmArgmin,
                         cudaFuncAttributeMaxDynamicSharedMemorySize, GSMEM);

    initKernel<<<32, 1024>>>();
    splitCB<<<KC, 256>>>(cb);
    splitZ<<<dim3(32, 8, 32), 256>>>(z);
    gemmArgmin<<<N_VEC / M_CTA, NTHR, GSMEM>>>();
    refineKernel<<<N_VEC / 8, 256>>>(z, cb);
    zqLossKernel<<<8192, 256>>>(z, cb, out);
    onehotKernel<<<N_VEC, 256>>>(out);
    finalizeKernel<<<1, 1024>>>(out);
}